// round 3
// baseline (speedup 1.0000x reference)
#include <cuda_runtime.h>
#include <cuda_bf16.h>
#include <stdint.h>
#include <math.h>

#define ASTR 40            /* padded smem stride in bf16 elems (80B rows) */
#define BK 32
#define KSPLIT 128
#define KCHUNK 2048

/* Scratch: __device__ globals (allocation-free rule) */
__device__ float g_q[32 * 512 * 512];
__device__ float g_k[32 * 512 * 512];
__device__ float g_ax[32 * 512 * 512];
__device__ float g_part[KSPLIT * 32 * 512];

/* ------------------------------------------------------------------ */
/* PTX helpers                                                         */
/* ------------------------------------------------------------------ */
__device__ __forceinline__ uint32_t sptr(const void* p) {
    return (uint32_t)__cvta_generic_to_shared(p);
}

__device__ __forceinline__ void ldsm_x4(uint32_t& r0, uint32_t& r1,
                                        uint32_t& r2, uint32_t& r3,
                                        uint32_t addr) {
    asm volatile("ldmatrix.sync.aligned.m8n8.x4.shared.b16 {%0,%1,%2,%3}, [%4];"
                 : "=r"(r0), "=r"(r1), "=r"(r2), "=r"(r3)
                 : "r"(addr));
}

__device__ __forceinline__ void mma_bf16(float* c, const uint32_t* a,
                                         const uint32_t* b) {
    asm volatile(
        "mma.sync.aligned.m16n8k16.row.col.f32.bf16.bf16.f32 "
        "{%0,%1,%2,%3}, {%4,%5,%6,%7}, {%8,%9}, {%0,%1,%2,%3};"
        : "+f"(c[0]), "+f"(c[1]), "+f"(c[2]), "+f"(c[3])
        : "r"(a[0]), "r"(a[1]), "r"(a[2]), "r"(a[3]),
          "r"(b[0]), "r"(b[1]));
}

/* fp32 -> bf16 hi/lo split */
__device__ __forceinline__ void split1(float v, uint16_t& h, uint16_t& l) {
    __nv_bfloat16 hb = __float2bfloat16(v);
    h = __bfloat16_as_ushort(hb);
    l = __bfloat16_as_ushort(__float2bfloat16(v - __bfloat162float(hb)));
}

__device__ __forceinline__ void split4(float4 v, uint2& uh, uint2& ul) {
    uint16_t h0, h1, h2, h3, l0, l1, l2, l3;
    split1(v.x, h0, l0);
    split1(v.y, h1, l1);
    split1(v.z, h2, l2);
    split1(v.w, h3, l3);
    uh.x = (uint32_t)h0 | ((uint32_t)h1 << 16);
    uh.y = (uint32_t)h2 | ((uint32_t)h3 << 16);
    ul.x = (uint32_t)l0 | ((uint32_t)l1 << 16);
    ul.y = (uint32_t)l2 | ((uint32_t)l3 << 16);
}

/* ------------------------------------------------------------------ */
/* Tile movement: gmem(fp32) -> regs -> smem(bf16 hi/lo)               */
/* direct: smem[m][k] from gmem rows; trans: gmem [k][n] -> smem[n][k] */
/* ------------------------------------------------------------------ */
template <int NIT>
__device__ __forceinline__ void g2r_direct(const float* __restrict__ g, int ldg,
                                           float4* v, int tid) {
#pragma unroll
    for (int i = 0; i < NIT; i++) {
        int idx = i * 256 + tid;
        v[i] = *(const float4*)(g + (size_t)(idx >> 3) * ldg + (idx & 7) * 4);
    }
}

template <int NIT>
__device__ __forceinline__ void r2s_direct(const float4* v, uint16_t* hi,
                                           uint16_t* lo, int tid) {
#pragma unroll
    for (int i = 0; i < NIT; i++) {
        int idx = i * 256 + tid;
        int m = idx >> 3;
        int k4 = (idx & 7) * 4;
        uint2 uh, ul;
        split4(v[i], uh, ul);
        *(uint2*)(hi + m * ASTR + k4) = uh;
        *(uint2*)(lo + m * ASTR + k4) = ul;
    }
}

template <int NIT>
__device__ __forceinline__ void g2r_trans(const float* __restrict__ g, int ldg,
                                          float4* v, int tid) {
#pragma unroll
    for (int i = 0; i < NIT; i++) {
        int idx = i * 256 + tid;
        v[i] = *(const float4*)(g + (size_t)(idx >> 5) * ldg + (idx & 31) * 4);
    }
}

template <int NIT>
__device__ __forceinline__ void r2s_trans(const float4* v, uint16_t* hi,
                                          uint16_t* lo, int tid) {
#pragma unroll
    for (int i = 0; i < NIT; i++) {
        int idx = i * 256 + tid;
        int k = idx >> 5;
        int n = (idx & 31) * 4;
        uint16_t h, l;
        split1(v[i].x, h, l);
        hi[(n + 0) * ASTR + k] = h;
        lo[(n + 0) * ASTR + k] = l;
        split1(v[i].y, h, l);
        hi[(n + 1) * ASTR + k] = h;
        lo[(n + 1) * ASTR + k] = l;
        split1(v[i].z, h, l);
        hi[(n + 2) * ASTR + k] = h;
        lo[(n + 2) * ASTR + k] = l;
        split1(v[i].w, h, l);
        hi[(n + 3) * ASTR + k] = h;
        lo[(n + 3) * ASTR + k] = l;
    }
}

/* ------------------------------------------------------------------ */
/* One BK=32 k-slab of a 128x128 CTA tile. 8 warps: wm in {0,1},       */
/* wn in {0..3}. Products kept: AhiBhi + AhiBlo + AloBhi.              */
/* ------------------------------------------------------------------ */
__device__ __forceinline__ void compute_tile128(uint32_t sAhi, uint32_t sAlo,
                                                uint32_t sBhi, uint32_t sBlo,
                                                int wm, int wn, int lane,
                                                float acc[4][4][4]) {
    const int lr = (lane & 7) + ((lane >> 3) & 1) * 8;
    const int lc = (lane >> 4) * 8;
#pragma unroll
    for (int ks = 0; ks < BK; ks += 16) {
        uint32_t bh[4][2];
        uint32_t bl[4][2];
#pragma unroll
        for (int p = 0; p < 2; p++) {
            uint32_t off = (uint32_t)(((wn * 32 + p * 16 + lr) * ASTR + ks + lc) * 2);
            uint32_t r0, r1, r2, r3;
            ldsm_x4(r0, r1, r2, r3, sBhi + off);
            bh[2 * p][0] = r0;
            bh[2 * p][1] = r2;
            bh[2 * p + 1][0] = r1;
            bh[2 * p + 1][1] = r3;
            ldsm_x4(r0, r1, r2, r3, sBlo + off);
            bl[2 * p][0] = r0;
            bl[2 * p][1] = r2;
            bl[2 * p + 1][0] = r1;
            bl[2 * p + 1][1] = r3;
        }
        uint32_t a[4][4];
#pragma unroll
        for (int mt = 0; mt < 4; mt++) {
            uint32_t off = (uint32_t)(((wm * 64 + mt * 16 + lr) * ASTR + ks + lc) * 2);
            ldsm_x4(a[mt][0], a[mt][1], a[mt][2], a[mt][3], sAhi + off);
        }
#pragma unroll
        for (int mt = 0; mt < 4; mt++) {
#pragma unroll
            for (int nt = 0; nt < 4; nt++) {
                mma_bf16(acc[mt][nt], a[mt], bh[nt]);
                mma_bf16(acc[mt][nt], a[mt], bl[nt]);
            }
        }
#pragma unroll
        for (int mt = 0; mt < 4; mt++) {
            uint32_t off = (uint32_t)(((wm * 64 + mt * 16 + lr) * ASTR + ks + lc) * 2);
            ldsm_x4(a[mt][0], a[mt][1], a[mt][2], a[mt][3], sAlo + off);
        }
#pragma unroll
        for (int mt = 0; mt < 4; mt++) {
#pragma unroll
            for (int nt = 0; nt < 4; nt++) {
                mma_bf16(acc[mt][nt], a[mt], bh[nt]);
            }
        }
    }
}

/* ------------------------------------------------------------------ */
/* Kernel 1: q/k projections. grid (4, 128, 2)                         */
/* ------------------------------------------------------------------ */
__global__ __launch_bounds__(256) void proj_kernel(
    const float* __restrict__ X, const float* __restrict__ Wq,
    const float* __restrict__ bq, const float* __restrict__ Wk,
    const float* __restrict__ bk) {
    const float* W = blockIdx.z ? Wk : Wq;
    const float* bias = blockIdx.z ? bk : bq;
    float* C = blockIdx.z ? g_k : g_q;

    __shared__ alignas(16) uint16_t As_hi[128 * ASTR];
    __shared__ alignas(16) uint16_t As_lo[128 * ASTR];
    __shared__ alignas(16) uint16_t Bs_hi[128 * ASTR];
    __shared__ alignas(16) uint16_t Bs_lo[128 * ASTR];

    const int tid = threadIdx.x;
    const int lane = tid & 31;
    const int wid = tid >> 5;
    const int wm = wid & 1;
    const int wn = wid >> 1;
    const int row0 = blockIdx.y * 128;
    const int col0 = blockIdx.x * 128;
    const uint32_t sAhi = sptr(As_hi);
    const uint32_t sAlo = sptr(As_lo);
    const uint32_t sBhi = sptr(Bs_hi);
    const uint32_t sBlo = sptr(Bs_lo);

    float acc[4][4][4] = {};
    float4 va[4];
    float4 vb[4];
    g2r_direct<4>(X + (size_t)row0 * 512, 512, va, tid);
    g2r_trans<4>(W + col0, 512, vb, tid);

    for (int k0 = 0; k0 < 512; k0 += BK) {
        __syncthreads();
        r2s_direct<4>(va, As_hi, As_lo, tid);
        r2s_trans<4>(vb, Bs_hi, Bs_lo, tid);
        __syncthreads();
        if (k0 + BK < 512) {
            g2r_direct<4>(X + (size_t)row0 * 512 + k0 + BK, 512, va, tid);
            g2r_trans<4>(W + (size_t)(k0 + BK) * 512 + col0, 512, vb, tid);
        }
        compute_tile128(sAhi, sAlo, sBhi, sBlo, wm, wn, lane, acc);
    }

    const int g = lane >> 2;
    const int tg2 = (lane & 3) * 2;
#pragma unroll
    for (int mt = 0; mt < 4; mt++) {
        int r = row0 + wm * 64 + mt * 16 + g;
#pragma unroll
        for (int nt = 0; nt < 4; nt++) {
            int c = col0 + wn * 32 + nt * 8 + tg2;
            float2 bv = *(const float2*)(bias + c);
            float2 o0;
            float2 o1;
            o0.x = acc[mt][nt][0] + bv.x;
            o0.y = acc[mt][nt][1] + bv.y;
            o1.x = acc[mt][nt][2] + bv.x;
            o1.y = acc[mt][nt][3] + bv.y;
            *(float2*)(C + (size_t)r * 512 + c) = o0;
            *(float2*)(C + (size_t)(r + 8) * 512 + c) = o1;
        }
    }
}

/* ------------------------------------------------------------------ */
/* Kernel 2: scores = sigmoid(q k^T / sqrt(512)). grid (4, 4, 32).     */
/* ------------------------------------------------------------------ */
__global__ __launch_bounds__(256) void scores_kernel(float* __restrict__ attn) {
    const int b = blockIdx.z;
    const float* Q = g_q + (size_t)b * 512 * 512;
    const float* Km = g_k + (size_t)b * 512 * 512;
    float* S = attn + (size_t)b * 512 * 512;

    __shared__ alignas(16) uint16_t As_hi[128 * ASTR];
    __shared__ alignas(16) uint16_t As_lo[128 * ASTR];
    __shared__ alignas(16) uint16_t Bs_hi[128 * ASTR];
    __shared__ alignas(16) uint16_t Bs_lo[128 * ASTR];

    const int tid = threadIdx.x;
    const int lane = tid & 31;
    const int wid = tid >> 5;
    const int wm = wid & 1;
    const int wn = wid >> 1;
    const int row0 = blockIdx.y * 128;
    const int col0 = blockIdx.x * 128;
    const uint32_t sAhi = sptr(As_hi);
    const uint32_t sAlo = sptr(As_lo);
    const uint32_t sBhi = sptr(Bs_hi);
    const uint32_t sBlo = sptr(Bs_lo);

    float acc[4][4][4] = {};
    float4 va[4];
    float4 vb[4];
    g2r_direct<4>(Q + (size_t)row0 * 512, 512, va, tid);
    g2r_direct<4>(Km + (size_t)col0 * 512, 512, vb, tid);

    for (int k0 = 0; k0 < 512; k0 += BK) {
        __syncthreads();
        r2s_direct<4>(va, As_hi, As_lo, tid);
        r2s_direct<4>(vb, Bs_hi, Bs_lo, tid);
        __syncthreads();
        if (k0 + BK < 512) {
            g2r_direct<4>(Q + (size_t)row0 * 512 + k0 + BK, 512, va, tid);
            g2r_direct<4>(Km + (size_t)col0 * 512 + k0 + BK, 512, vb, tid);
        }
        compute_tile128(sAhi, sAlo, sBhi, sBlo, wm, wn, lane, acc);
    }

    const float scale = 0.04419417382415922f; /* 1/sqrt(512) */
    const int g = lane >> 2;
    const int tg2 = (lane & 3) * 2;
#pragma unroll
    for (int mt = 0; mt < 4; mt++) {
        int r = row0 + wm * 64 + mt * 16 + g;
#pragma unroll
        for (int nt = 0; nt < 4; nt++) {
            int c = col0 + wn * 32 + nt * 8 + tg2;
            float2 o0;
            float2 o1;
            o0.x = 1.f / (1.f + expf(-acc[mt][nt][0] * scale));
            o0.y = 1.f / (1.f + expf(-acc[mt][nt][1] * scale));
            o1.x = 1.f / (1.f + expf(-acc[mt][nt][2] * scale));
            o1.y = 1.f / (1.f + expf(-acc[mt][nt][3] * scale));
            *(float2*)(S + (size_t)r * 512 + c) = o0;
            *(float2*)(S + (size_t)(r + 8) * 512 + c) = o1;
        }
    }
}

/* ------------------------------------------------------------------ */
/* Kernel 3: row softmax in-place over 512-wide rows. grid 16384.      */
/* ------------------------------------------------------------------ */
__global__ __launch_bounds__(256) void softmax_kernel(float* __restrict__ attn) {
    float* p = attn + (size_t)blockIdx.x * 512;
    const int tid = threadIdx.x;
    float e0 = expf(p[tid]);
    float e1 = expf(p[tid + 256]);
    float s = e0 + e1;
#pragma unroll
    for (int o = 16; o > 0; o >>= 1) {
        s += __shfl_xor_sync(0xffffffffu, s, o);
    }
    __shared__ float ws[8];
    if ((tid & 31) == 0) {
        ws[tid >> 5] = s;
    }
    __syncthreads();
    if (tid < 8) {
        float t = ws[tid];
#pragma unroll
        for (int o = 4; o > 0; o >>= 1) {
            t += __shfl_xor_sync(0xffu, t, o);
        }
        if (tid == 0) {
            ws[0] = t;
        }
    }
    __syncthreads();
    const float inv = 1.f / ws[0];
    p[tid] = e0 * inv;
    p[tid + 256] = e1 * inv;
}

/* ------------------------------------------------------------------ */
/* Kernel 4: ax[b] = attn[b] @ x[b]. grid (4, 4, 32).                  */
/* ------------------------------------------------------------------ */
__global__ __launch_bounds__(256) void ax_kernel(const float* __restrict__ attn,
                                                 const float* __restrict__ x) {
    const int b = blockIdx.z;
    const float* A = attn + (size_t)b * 512 * 512;
    const float* Xb = x + (size_t)b * 512 * 512;
    float* C = g_ax + (size_t)b * 512 * 512;

    __shared__ alignas(16) uint16_t As_hi[128 * ASTR];
    __shared__ alignas(16) uint16_t As_lo[128 * ASTR];
    __shared__ alignas(16) uint16_t Bs_hi[128 * ASTR];
    __shared__ alignas(16) uint16_t Bs_lo[128 * ASTR];

    const int tid = threadIdx.x;
    const int lane = tid & 31;
    const int wid = tid >> 5;
    const int wm = wid & 1;
    const int wn = wid >> 1;
    const int row0 = blockIdx.y * 128;
    const int col0 = blockIdx.x * 128;
    const uint32_t sAhi = sptr(As_hi);
    const uint32_t sAlo = sptr(As_lo);
    const uint32_t sBhi = sptr(Bs_hi);
    const uint32_t sBlo = sptr(Bs_lo);

    float acc[4][4][4] = {};
    float4 va[4];
    float4 vb[4];
    g2r_direct<4>(A + (size_t)row0 * 512, 512, va, tid);
    g2r_trans<4>(Xb + col0, 512, vb, tid);

    for (int k0 = 0; k0 < 512; k0 += BK) {
        __syncthreads();
        r2s_direct<4>(va, As_hi, As_lo, tid);
        r2s_trans<4>(vb, Bs_hi, Bs_lo, tid);
        __syncthreads();
        if (k0 + BK < 512) {
            g2r_direct<4>(A + (size_t)row0 * 512 + k0 + BK, 512, va, tid);
            g2r_trans<4>(Xb + (size_t)(k0 + BK) * 512 + col0, 512, vb, tid);
        }
        compute_tile128(sAhi, sAlo, sBhi, sBlo, wm, wn, lane, acc);
    }

    const int g = lane >> 2;
    const int tg2 = (lane & 3) * 2;
#pragma unroll
    for (int mt = 0; mt < 4; mt++) {
        int r = row0 + wm * 64 + mt * 16 + g;
#pragma unroll
        for (int nt = 0; nt < 4; nt++) {
            int c = col0 + wn * 32 + nt * 8 + tg2;
            float2 o0;
            float2 o1;
            o0.x = acc[mt][nt][0];
            o0.y = acc[mt][nt][1];
            o1.x = acc[mt][nt][2];
            o1.y = acc[mt][nt][3];
            *(float2*)(C + (size_t)r * 512 + c) = o0;
            *(float2*)(C + (size_t)(r + 8) * 512 + c) = o1;
        }
    }
}

/* ------------------------------------------------------------------ */
/* Kernel 5: split-K partials of out = ax.reshape(32,262144) @ Wm.     */
/* grid (4, KSPLIT). CTA tile 32x128, K chunk = KCHUNK.                */
/* ------------------------------------------------------------------ */
__global__ __launch_bounds__(256) void final_kernel(const float* __restrict__ Wm) {
    __shared__ alignas(16) uint16_t As_hi[32 * ASTR];
    __shared__ alignas(16) uint16_t As_lo[32 * ASTR];
    __shared__ alignas(16) uint16_t Bs_hi[128 * ASTR];
    __shared__ alignas(16) uint16_t Bs_lo[128 * ASTR];

    const int tid = threadIdx.x;
    const int lane = tid & 31;
    const int wid = tid >> 5;
    const int col0 = blockIdx.x * 128;
    const size_t kbase = (size_t)blockIdx.y * KCHUNK;
    const uint32_t sAhi = sptr(As_hi);
    const uint32_t sAlo = sptr(As_lo);
    const uint32_t sBhi = sptr(Bs_hi);
    const uint32_t sBlo = sptr(Bs_lo);

    float acc[2][2][4] = {};
    float4 va[1];
    float4 vb[4];
    g2r_direct<1>(g_ax + kbase, 262144, va, tid);
    g2r_trans<4>(Wm + kbase * 512 + col0, 512, vb, tid);

    const int lr = (lane & 7) + ((lane >> 3) & 1) * 8;
    const int lc = (lane >> 4) * 8;

    for (int k0 = 0; k0 < KCHUNK; k0 += BK) {
        __syncthreads();
        r2s_direct<1>(va, As_hi, As_lo, tid);
        r2s_trans<4>(vb, Bs_hi, Bs_lo, tid);
        __syncthreads();
        if (k0 + BK < KCHUNK) {
            g2r_direct<1>(g_ax + kbase + k0 + BK, 262144, va, tid);
            g2r_trans<4>(Wm + (kbase + k0 + BK) * 512 + col0, 512, vb, tid);
        }
#pragma unroll
        for (int ks = 0; ks < BK; ks += 16) {
            uint32_t bh[2][2];
            uint32_t bl[2][2];
            uint32_t offb = (uint32_t)(((wid * 16 + lr) * ASTR + ks + lc) * 2);
            uint32_t r0, r1, r2, r3;
            ldsm_x4(r0, r1, r2, r3, sBhi + offb);
            bh[0][0] = r0;
            bh[0][1] = r2;
            bh[1][0] = r1;
            bh[1][1] = r3;
            ldsm_x4(r0, r1, r2, r3, sBlo + offb);
            bl[0][0] = r0;
            bl[0][1] = r2;
            bl[1][0] = r1;
            bl[1][1] = r3;
            uint32_t a[2][4];
#pragma unroll
            for (int mt = 0; mt < 2; mt++) {
                uint32_t offa = (uint32_t)(((mt * 16 + lr) * ASTR + ks + lc) * 2);
                ldsm_x4(a[mt][0], a[mt][1], a[mt][2], a[mt][3], sAhi + offa);
            }
#pragma unroll
            for (int mt = 0; mt < 2; mt++) {
#pragma unroll
                for (int nt = 0; nt < 2; nt++) {
                    mma_bf16(acc[mt][nt], a[mt], bh[nt]);
                    mma_bf16(acc[mt][nt], a[mt], bl[nt]);
                }
            }
#pragma unroll
            for (int mt = 0; mt < 2; mt++) {
                uint32_t offa = (uint32_t)(((mt * 16 + lr) * ASTR + ks + lc) * 2);
                ldsm_x4(a[mt][0], a[mt][1], a[mt][2], a[mt][3], sAlo + offa);
            }
#pragma unroll
            for (int mt = 0; mt < 2; mt++) {
#pragma unroll
                for (int nt = 0; nt < 2; nt++) {
                    mma_bf16(acc[mt][nt], a[mt], bh[nt]);
                }
            }
        }
    }

    const int g = lane >> 2;
    const int tg2 = (lane & 3) * 2;
    float* P = g_part + (size_t)blockIdx.y * 16384;
#pragma unroll
    for (int mt = 0; mt < 2; mt++) {
        int r = mt * 16 + g;
#pragma unroll
        for (int nt = 0; nt < 2; nt++) {
            int c = col0 + wid * 16 + nt * 8 + tg2;
            float2 o0;
            float2 o1;
            o0.x = acc[mt][nt][0];
            o0.y = acc[mt][nt][1];
            o1.x = acc[mt][nt][2];
            o1.y = acc[mt][nt][3];
            *(float2*)(P + (size_t)r * 512 + c) = o0;
            *(float2*)(P + (size_t)(r + 8) * 512 + c) = o1;
        }
    }
}

/* ------------------------------------------------------------------ */
/* Kernel 6: deterministic split-K reduce + bias. grid 64 x 256.       */
/* ------------------------------------------------------------------ */
__global__ __launch_bounds__(256) void reduce_kernel(float* __restrict__ out,
                                                     const float* __restrict__ bm) {
    const int idx = blockIdx.x * 256 + threadIdx.x; /* == m*512 + n */
    const int n = idx & 511;
    float sum = bm[n];
#pragma unroll 8
    for (int s = 0; s < KSPLIT; s++) {
        sum += g_part[(size_t)s * 16384 + idx];
    }
    out[idx] = sum;
}

/* ------------------------------------------------------------------ */
extern "C" void kernel_launch(void* const* d_in, const int* in_sizes, int n_in,
                              void* d_out, int out_size) {
    const float* x = (const float*)d_in[0];
    const float* Wq = (const float*)d_in[1];
    const float* bq = (const float*)d_in[2];
    const float* Wk = (const float*)d_in[3];
    const float* bk = (const float*)d_in[4];
    const float* Wm = (const float*)d_in[5];
    const float* bm = (const float*)d_in[6];

    float* out = (float*)d_out;   /* [32, 512] */
    float* attn = out + 32 * 512; /* [32, 512, 512] */

    proj_kernel<<<dim3(4, 128, 2), 256>>>(x, Wq, bq, Wk, bk);
    scores_kernel<<<dim3(4, 4, 32), 256>>>(attn);
    softmax_kernel<<<16384, 256>>>(attn);
    ax_kernel<<<dim3(4, 4, 32), 256>>>(attn, x);
    final_kernel<<<dim3(4, KSPLIT), 256>>>(Wm);
    reduce_kernel<<<64, 256>>>(out, bm);
}

// round 4
// speedup vs baseline: 1.2773x; 1.2773x over previous
#include <cuda_runtime.h>
#include <cuda_fp16.h>
#include <stdint.h>
#include <math.h>

#define ASTR 40            /* padded smem stride in fp16 elems (80B rows) */
#define BK 32
#define KSPLIT 128
#define KCHUNK 2048

/* Scratch: __device__ globals (allocation-free rule) */
__device__ float g_q[32 * 512 * 512];
__device__ float g_k[32 * 512 * 512];
__device__ float g_ax[32 * 512 * 512];
__device__ float g_part[KSPLIT * 32 * 512];

/* ------------------------------------------------------------------ */
/* PTX helpers                                                         */
/* ------------------------------------------------------------------ */
__device__ __forceinline__ uint32_t sptr(const void* p) {
    return (uint32_t)__cvta_generic_to_shared(p);
}

__device__ __forceinline__ void ldsm_x4(uint32_t& r0, uint32_t& r1,
                                        uint32_t& r2, uint32_t& r3,
                                        uint32_t addr) {
    asm volatile("ldmatrix.sync.aligned.m8n8.x4.shared.b16 {%0,%1,%2,%3}, [%4];"
                 : "=r"(r0), "=r"(r1), "=r"(r2), "=r"(r3)
                 : "r"(addr));
}

__device__ __forceinline__ void mma_f16(float* c, const uint32_t* a,
                                        const uint32_t* b) {
    asm volatile(
        "mma.sync.aligned.m16n8k16.row.col.f32.f16.f16.f32 "
        "{%0,%1,%2,%3}, {%4,%5,%6,%7}, {%8,%9}, {%0,%1,%2,%3};"
        : "+f"(c[0]), "+f"(c[1]), "+f"(c[2]), "+f"(c[3])
        : "r"(a[0]), "r"(a[1]), "r"(a[2]), "r"(a[3]),
          "r"(b[0]), "r"(b[1]));
}

/* fp32 -> fp16 plain */
__device__ __forceinline__ uint16_t h1(float v) {
    __half h = __float2half_rn(v);
    return *reinterpret_cast<uint16_t*>(&h);
}
/* fp32 -> fp16 hi/lo split */
__device__ __forceinline__ void split1h(float v, uint16_t& hh, uint16_t& ll) {
    __half hb = __float2half_rn(v);
    hh = *reinterpret_cast<uint16_t*>(&hb);
    __half lb = __float2half_rn(v - __half2float(hb));
    ll = *reinterpret_cast<uint16_t*>(&lb);
}

/* ------------------------------------------------------------------ */
/* gmem(fp32) -> regs                                                  */
/* ------------------------------------------------------------------ */
template <int NIT>
__device__ __forceinline__ void g2r_direct(const float* __restrict__ g, int ldg,
                                           float4* v, int tid) {
#pragma unroll
    for (int i = 0; i < NIT; i++) {
        int idx = i * 256 + tid;
        v[i] = *(const float4*)(g + (size_t)(idx >> 3) * ldg + (idx & 7) * 4);
    }
}

template <int NIT>
__device__ __forceinline__ void g2r_trans(const float* __restrict__ g, int ldg,
                                          float4* v, int tid) {
#pragma unroll
    for (int i = 0; i < NIT; i++) {
        int idx = i * 256 + tid;
        v[i] = *(const float4*)(g + (size_t)(idx >> 5) * ldg + (idx & 31) * 4);
    }
}

/* ------------------------------------------------------------------ */
/* regs -> smem: plain fp16                                            */
/* ------------------------------------------------------------------ */
template <int NIT>
__device__ __forceinline__ void r2s_direct_h(const float4* v, uint16_t* s, int tid) {
#pragma unroll
    for (int i = 0; i < NIT; i++) {
        int idx = i * 256 + tid;
        int m = idx >> 3;
        int k4 = (idx & 7) * 4;
        __half2 p0 = __floats2half2_rn(v[i].x, v[i].y);
        __half2 p1 = __floats2half2_rn(v[i].z, v[i].w);
        uint2 u;
        u.x = *reinterpret_cast<uint32_t*>(&p0);
        u.y = *reinterpret_cast<uint32_t*>(&p1);
        *(uint2*)(s + m * ASTR + k4) = u;
    }
}

template <int NIT>
__device__ __forceinline__ void r2s_trans_h(const float4* v, uint16_t* s, int tid) {
#pragma unroll
    for (int i = 0; i < NIT; i++) {
        int idx = i * 256 + tid;
        int k = idx >> 5;
        int n = (idx & 31) * 4;
        s[(n + 0) * ASTR + k] = h1(v[i].x);
        s[(n + 1) * ASTR + k] = h1(v[i].y);
        s[(n + 2) * ASTR + k] = h1(v[i].z);
        s[(n + 3) * ASTR + k] = h1(v[i].w);
    }
}

/* ------------------------------------------------------------------ */
/* regs -> smem: fp16 hi/lo split                                      */
/* ------------------------------------------------------------------ */
template <int NIT>
__device__ __forceinline__ void r2s_direct_s(const float4* v, uint16_t* hi,
                                             uint16_t* lo, int tid) {
#pragma unroll
    for (int i = 0; i < NIT; i++) {
        int idx = i * 256 + tid;
        int m = idx >> 3;
        int k4 = (idx & 7) * 4;
        uint16_t a0, a1, a2, a3, b0, b1, b2, b3;
        split1h(v[i].x, a0, b0);
        split1h(v[i].y, a1, b1);
        split1h(v[i].z, a2, b2);
        split1h(v[i].w, a3, b3);
        uint2 uh, ul;
        uh.x = (uint32_t)a0 | ((uint32_t)a1 << 16);
        uh.y = (uint32_t)a2 | ((uint32_t)a3 << 16);
        ul.x = (uint32_t)b0 | ((uint32_t)b1 << 16);
        ul.y = (uint32_t)b2 | ((uint32_t)b3 << 16);
        *(uint2*)(hi + m * ASTR + k4) = uh;
        *(uint2*)(lo + m * ASTR + k4) = ul;
    }
}

template <int NIT>
__device__ __forceinline__ void r2s_trans_s(const float4* v, uint16_t* hi,
                                            uint16_t* lo, int tid) {
#pragma unroll
    for (int i = 0; i < NIT; i++) {
        int idx = i * 256 + tid;
        int k = idx >> 5;
        int n = (idx & 31) * 4;
        uint16_t hh, ll;
        split1h(v[i].x, hh, ll);
        hi[(n + 0) * ASTR + k] = hh;
        lo[(n + 0) * ASTR + k] = ll;
        split1h(v[i].y, hh, ll);
        hi[(n + 1) * ASTR + k] = hh;
        lo[(n + 1) * ASTR + k] = ll;
        split1h(v[i].z, hh, ll);
        hi[(n + 2) * ASTR + k] = hh;
        lo[(n + 2) * ASTR + k] = ll;
        split1h(v[i].w, hh, ll);
        hi[(n + 3) * ASTR + k] = hh;
        lo[(n + 3) * ASTR + k] = ll;
    }
}

/* ------------------------------------------------------------------ */
/* Plain fp16 compute: one BK slab, 128x128 CTA, 8 warps (wm 2, wn 4). */
/* ------------------------------------------------------------------ */
__device__ __forceinline__ void compute128_h(uint32_t sA, uint32_t sB,
                                             int wm, int wn, int lane,
                                             float acc[4][4][4]) {
    const int lr = (lane & 7) + ((lane >> 3) & 1) * 8;
    const int lc = (lane >> 4) * 8;
#pragma unroll
    for (int ks = 0; ks < BK; ks += 16) {
        uint32_t b[4][2];
#pragma unroll
        for (int p = 0; p < 2; p++) {
            uint32_t off = (uint32_t)(((wn * 32 + p * 16 + lr) * ASTR + ks + lc) * 2);
            uint32_t r0, r1, r2, r3;
            ldsm_x4(r0, r1, r2, r3, sB + off);
            b[2 * p][0] = r0;
            b[2 * p][1] = r2;
            b[2 * p + 1][0] = r1;
            b[2 * p + 1][1] = r3;
        }
        uint32_t a[4][4];
#pragma unroll
        for (int mt = 0; mt < 4; mt++) {
            uint32_t off = (uint32_t)(((wm * 64 + mt * 16 + lr) * ASTR + ks + lc) * 2);
            ldsm_x4(a[mt][0], a[mt][1], a[mt][2], a[mt][3], sA + off);
        }
#pragma unroll
        for (int mt = 0; mt < 4; mt++) {
#pragma unroll
            for (int nt = 0; nt < 4; nt++) {
                mma_f16(acc[mt][nt], a[mt], b[nt]);
            }
        }
    }
}

/* ------------------------------------------------------------------ */
/* Split fp16 compute (3 terms): one BK slab, 128x128 CTA.             */
/* ------------------------------------------------------------------ */
__device__ __forceinline__ void compute128_s(uint32_t sAhi, uint32_t sAlo,
                                             uint32_t sBhi, uint32_t sBlo,
                                             int wm, int wn, int lane,
                                             float acc[4][4][4]) {
    const int lr = (lane & 7) + ((lane >> 3) & 1) * 8;
    const int lc = (lane >> 4) * 8;
#pragma unroll
    for (int ks = 0; ks < BK; ks += 16) {
        uint32_t bh[4][2];
        uint32_t bl[4][2];
#pragma unroll
        for (int p = 0; p < 2; p++) {
            uint32_t off = (uint32_t)(((wn * 32 + p * 16 + lr) * ASTR + ks + lc) * 2);
            uint32_t r0, r1, r2, r3;
            ldsm_x4(r0, r1, r2, r3, sBhi + off);
            bh[2 * p][0] = r0;
            bh[2 * p][1] = r2;
            bh[2 * p + 1][0] = r1;
            bh[2 * p + 1][1] = r3;
            ldsm_x4(r0, r1, r2, r3, sBlo + off);
            bl[2 * p][0] = r0;
            bl[2 * p][1] = r2;
            bl[2 * p + 1][0] = r1;
            bl[2 * p + 1][1] = r3;
        }
        uint32_t a[4][4];
#pragma unroll
        for (int mt = 0; mt < 4; mt++) {
            uint32_t off = (uint32_t)(((wm * 64 + mt * 16 + lr) * ASTR + ks + lc) * 2);
            ldsm_x4(a[mt][0], a[mt][1], a[mt][2], a[mt][3], sAhi + off);
        }
#pragma unroll
        for (int mt = 0; mt < 4; mt++) {
#pragma unroll
            for (int nt = 0; nt < 4; nt++) {
                mma_f16(acc[mt][nt], a[mt], bh[nt]);
                mma_f16(acc[mt][nt], a[mt], bl[nt]);
            }
        }
#pragma unroll
        for (int mt = 0; mt < 4; mt++) {
            uint32_t off = (uint32_t)(((wm * 64 + mt * 16 + lr) * ASTR + ks + lc) * 2);
            ldsm_x4(a[mt][0], a[mt][1], a[mt][2], a[mt][3], sAlo + off);
        }
#pragma unroll
        for (int mt = 0; mt < 4; mt++) {
#pragma unroll
            for (int nt = 0; nt < 4; nt++) {
                mma_f16(acc[mt][nt], a[mt], bh[nt]);
            }
        }
    }
}

/* ------------------------------------------------------------------ */
/* Kernel 1: q/k projections (plain fp16, double-buffered).            */
/* grid (4, 128, 2), 256 thr, 2 CTAs/SM.                               */
/* ------------------------------------------------------------------ */
__global__ __launch_bounds__(256, 2) void proj_kernel(
    const float* __restrict__ X, const float* __restrict__ Wq,
    const float* __restrict__ bq, const float* __restrict__ Wk,
    const float* __restrict__ bk) {
    const float* W = blockIdx.z ? Wk : Wq;
    const float* bias = blockIdx.z ? bk : bq;
    float* C = blockIdx.z ? g_k : g_q;

    __shared__ alignas(16) uint16_t As[2][128 * ASTR];
    __shared__ alignas(16) uint16_t Bs[2][128 * ASTR];

    const int tid = threadIdx.x;
    const int lane = tid & 31;
    const int wid = tid >> 5;
    const int wm = wid & 1;
    const int wn = wid >> 1;
    const int row0 = blockIdx.y * 128;
    const int col0 = blockIdx.x * 128;

    float acc[4][4][4] = {};
    float4 va[4];
    float4 vb[4];

    g2r_direct<4>(X + (size_t)row0 * 512, 512, va, tid);
    g2r_trans<4>(W + col0, 512, vb, tid);
    r2s_direct_h<4>(va, As[0], tid);
    r2s_trans_h<4>(vb, Bs[0], tid);
    g2r_direct<4>(X + (size_t)row0 * 512 + BK, 512, va, tid);
    g2r_trans<4>(W + (size_t)BK * 512 + col0, 512, vb, tid);
    __syncthreads();

    for (int k0 = 0; k0 < 512; k0 += BK) {
        int cur = (k0 >> 5) & 1;
        if (k0 + BK < 512) {
            r2s_direct_h<4>(va, As[cur ^ 1], tid);
            r2s_trans_h<4>(vb, Bs[cur ^ 1], tid);
        }
        if (k0 + 2 * BK < 512) {
            g2r_direct<4>(X + (size_t)row0 * 512 + k0 + 2 * BK, 512, va, tid);
            g2r_trans<4>(W + (size_t)(k0 + 2 * BK) * 512 + col0, 512, vb, tid);
        }
        compute128_h(sptr(As[cur]), sptr(Bs[cur]), wm, wn, lane, acc);
        __syncthreads();
    }

    const int g = lane >> 2;
    const int tg2 = (lane & 3) * 2;
#pragma unroll
    for (int mt = 0; mt < 4; mt++) {
        int r = row0 + wm * 64 + mt * 16 + g;
#pragma unroll
        for (int nt = 0; nt < 4; nt++) {
            int c = col0 + wn * 32 + nt * 8 + tg2;
            float2 bv = *(const float2*)(bias + c);
            float2 o0;
            float2 o1;
            o0.x = acc[mt][nt][0] + bv.x;
            o0.y = acc[mt][nt][1] + bv.y;
            o1.x = acc[mt][nt][2] + bv.x;
            o1.y = acc[mt][nt][3] + bv.y;
            *(float2*)(C + (size_t)r * 512 + c) = o0;
            *(float2*)(C + (size_t)(r + 8) * 512 + c) = o1;
        }
    }
}

/* ------------------------------------------------------------------ */
/* Kernel 2: scores = sigmoid(q k^T / sqrt(512)) (plain fp16, DB).     */
/* grid (4, 4, 32).                                                    */
/* ------------------------------------------------------------------ */
__global__ __launch_bounds__(256, 2) void scores_kernel(float* __restrict__ attn) {
    const int b = blockIdx.z;
    const float* Q = g_q + (size_t)b * 512 * 512;
    const float* Km = g_k + (size_t)b * 512 * 512;
    float* S = attn + (size_t)b * 512 * 512;

    __shared__ alignas(16) uint16_t As[2][128 * ASTR];
    __shared__ alignas(16) uint16_t Bs[2][128 * ASTR];

    const int tid = threadIdx.x;
    const int lane = tid & 31;
    const int wid = tid >> 5;
    const int wm = wid & 1;
    const int wn = wid >> 1;
    const int row0 = blockIdx.y * 128;
    const int col0 = blockIdx.x * 128;

    float acc[4][4][4] = {};
    float4 va[4];
    float4 vb[4];

    g2r_direct<4>(Q + (size_t)row0 * 512, 512, va, tid);
    g2r_direct<4>(Km + (size_t)col0 * 512, 512, vb, tid);
    r2s_direct_h<4>(va, As[0], tid);
    r2s_direct_h<4>(vb, Bs[0], tid);
    g2r_direct<4>(Q + (size_t)row0 * 512 + BK, 512, va, tid);
    g2r_direct<4>(Km + (size_t)col0 * 512 + BK, 512, vb, tid);
    __syncthreads();

    for (int k0 = 0; k0 < 512; k0 += BK) {
        int cur = (k0 >> 5) & 1;
        if (k0 + BK < 512) {
            r2s_direct_h<4>(va, As[cur ^ 1], tid);
            r2s_direct_h<4>(vb, Bs[cur ^ 1], tid);
        }
        if (k0 + 2 * BK < 512) {
            g2r_direct<4>(Q + (size_t)row0 * 512 + k0 + 2 * BK, 512, va, tid);
            g2r_direct<4>(Km + (size_t)col0 * 512 + k0 + 2 * BK, 512, vb, tid);
        }
        compute128_h(sptr(As[cur]), sptr(Bs[cur]), wm, wn, lane, acc);
        __syncthreads();
    }

    const float scale = 0.04419417382415922f; /* 1/sqrt(512) */
    const int g = lane >> 2;
    const int tg2 = (lane & 3) * 2;
#pragma unroll
    for (int mt = 0; mt < 4; mt++) {
        int r = row0 + wm * 64 + mt * 16 + g;
#pragma unroll
        for (int nt = 0; nt < 4; nt++) {
            int c = col0 + wn * 32 + nt * 8 + tg2;
            float2 o0;
            float2 o1;
            o0.x = 1.f / (1.f + expf(-acc[mt][nt][0] * scale));
            o0.y = 1.f / (1.f + expf(-acc[mt][nt][1] * scale));
            o1.x = 1.f / (1.f + expf(-acc[mt][nt][2] * scale));
            o1.y = 1.f / (1.f + expf(-acc[mt][nt][3] * scale));
            *(float2*)(S + (size_t)r * 512 + c) = o0;
            *(float2*)(S + (size_t)(r + 8) * 512 + c) = o1;
        }
    }
}

/* ------------------------------------------------------------------ */
/* Kernel 3: row softmax in-place over 512-wide rows. grid 16384.      */
/* ------------------------------------------------------------------ */
__global__ __launch_bounds__(256) void softmax_kernel(float* __restrict__ attn) {
    float* p = attn + (size_t)blockIdx.x * 512;
    const int tid = threadIdx.x;
    float e0 = expf(p[tid]);
    float e1 = expf(p[tid + 256]);
    float s = e0 + e1;
#pragma unroll
    for (int o = 16; o > 0; o >>= 1) {
        s += __shfl_xor_sync(0xffffffffu, s, o);
    }
    __shared__ float ws[8];
    if ((tid & 31) == 0) {
        ws[tid >> 5] = s;
    }
    __syncthreads();
    if (tid < 8) {
        float t = ws[tid];
#pragma unroll
        for (int o = 4; o > 0; o >>= 1) {
            t += __shfl_xor_sync(0xffu, t, o);
        }
        if (tid == 0) {
            ws[0] = t;
        }
    }
    __syncthreads();
    const float inv = 1.f / ws[0];
    p[tid] = e0 * inv;
    p[tid + 256] = e1 * inv;
}

/* ------------------------------------------------------------------ */
/* Kernel 4: ax[b] = attn[b] @ x[b] (fp16 3-term split, DB, dyn smem). */
/* grid (4, 4, 32). Dynamic smem: 2 stages x (Ahi,Alo,Bhi,Blo).        */
/* ------------------------------------------------------------------ */
#define AXELEMS (128 * ASTR)           /* 5120 elems per array */
#define AXSTAGE (4 * AXELEMS)          /* 20480 elems per stage */
#define AXBYTES (2 * AXSTAGE * 2)      /* 81920 bytes total */

__global__ __launch_bounds__(256) void ax_kernel(const float* __restrict__ attn,
                                                 const float* __restrict__ x) {
    extern __shared__ uint16_t dsm[];
    const int b = blockIdx.z;
    const float* A = attn + (size_t)b * 512 * 512;
    const float* Xb = x + (size_t)b * 512 * 512;
    float* C = g_ax + (size_t)b * 512 * 512;

    const int tid = threadIdx.x;
    const int lane = tid & 31;
    const int wid = tid >> 5;
    const int wm = wid & 1;
    const int wn = wid >> 1;
    const int row0 = blockIdx.y * 128;
    const int col0 = blockIdx.x * 128;

    float acc[4][4][4] = {};
    float4 va[4];
    float4 vb[4];

    g2r_direct<4>(A + (size_t)row0 * 512, 512, va, tid);
    g2r_trans<4>(Xb + col0, 512, vb, tid);
    r2s_direct_s<4>(va, dsm, dsm + AXELEMS, tid);
    r2s_trans_s<4>(vb, dsm + 2 * AXELEMS, dsm + 3 * AXELEMS, tid);
    g2r_direct<4>(A + (size_t)row0 * 512 + BK, 512, va, tid);
    g2r_trans<4>(Xb + (size_t)BK * 512 + col0, 512, vb, tid);
    __syncthreads();

    for (int k0 = 0; k0 < 512; k0 += BK) {
        int cur = (k0 >> 5) & 1;
        uint16_t* stg = dsm + (cur ^ 1) * AXSTAGE;
        if (k0 + BK < 512) {
            r2s_direct_s<4>(va, stg, stg + AXELEMS, tid);
            r2s_trans_s<4>(vb, stg + 2 * AXELEMS, stg + 3 * AXELEMS, tid);
        }
        if (k0 + 2 * BK < 512) {
            g2r_direct<4>(A + (size_t)row0 * 512 + k0 + 2 * BK, 512, va, tid);
            g2r_trans<4>(Xb + (size_t)(k0 + 2 * BK) * 512 + col0, 512, vb, tid);
        }
        uint32_t base = sptr(dsm) + cur * AXSTAGE * 2;
        compute128_s(base, base + AXELEMS * 2, base + 4 * AXELEMS,
                     base + 6 * AXELEMS, wm, wn, lane, acc);
        __syncthreads();
    }

    const int g = lane >> 2;
    const int tg2 = (lane & 3) * 2;
#pragma unroll
    for (int mt = 0; mt < 4; mt++) {
        int r = row0 + wm * 64 + mt * 16 + g;
#pragma unroll
        for (int nt = 0; nt < 4; nt++) {
            int c = col0 + wn * 32 + nt * 8 + tg2;
            float2 o0;
            float2 o1;
            o0.x = acc[mt][nt][0];
            o0.y = acc[mt][nt][1];
            o1.x = acc[mt][nt][2];
            o1.y = acc[mt][nt][3];
            *(float2*)(C + (size_t)r * 512 + c) = o0;
            *(float2*)(C + (size_t)(r + 8) * 512 + c) = o1;
        }
    }
}

/* ------------------------------------------------------------------ */
/* Kernel 5: split-K partials of out = ax.reshape(32,262144) @ Wm.     */
/* fp16 3-term split, DB, dyn smem. grid (4, KSPLIT), tile 32x128.     */
/* ------------------------------------------------------------------ */
#define FAEL (32 * ASTR)               /* 1280 elems per A array */
#define FBEL (128 * ASTR)              /* 5120 elems per B array */
#define FSTAGE (2 * FAEL + 2 * FBEL)   /* 12800 elems per stage */
#define FBYTES (2 * FSTAGE * 2)        /* 51200 bytes total */

__global__ __launch_bounds__(256) void final_kernel(const float* __restrict__ Wm) {
    extern __shared__ uint16_t dsm[];

    const int tid = threadIdx.x;
    const int lane = tid & 31;
    const int wid = tid >> 5;
    const int col0 = blockIdx.x * 128;
    const size_t kbase = (size_t)blockIdx.y * KCHUNK;

    float acc[2][2][4] = {};
    float4 va[1];
    float4 vb[4];

    g2r_direct<1>(g_ax + kbase, 262144, va, tid);
    g2r_trans<4>(Wm + kbase * 512 + col0, 512, vb, tid);
    r2s_direct_s<1>(va, dsm, dsm + FAEL, tid);
    r2s_trans_s<4>(vb, dsm + 2 * FAEL, dsm + 2 * FAEL + FBEL, tid);
    g2r_direct<1>(g_ax + kbase + BK, 262144, va, tid);
    g2r_trans<4>(Wm + (kbase + BK) * 512 + col0, 512, vb, tid);
    __syncthreads();

    const int lr = (lane & 7) + ((lane >> 3) & 1) * 8;
    const int lc = (lane >> 4) * 8;

    for (int k0 = 0; k0 < KCHUNK; k0 += BK) {
        int cur = (k0 >> 5) & 1;
        uint16_t* stg = dsm + (cur ^ 1) * FSTAGE;
        if (k0 + BK < KCHUNK) {
            r2s_direct_s<1>(va, stg, stg + FAEL, tid);
            r2s_trans_s<4>(vb, stg + 2 * FAEL, stg + 2 * FAEL + FBEL, tid);
        }
        if (k0 + 2 * BK < KCHUNK) {
            g2r_direct<1>(g_ax + kbase + k0 + 2 * BK, 262144, va, tid);
            g2r_trans<4>(Wm + (kbase + k0 + 2 * BK) * 512 + col0, 512, vb, tid);
        }
        uint32_t base = sptr(dsm) + cur * FSTAGE * 2;
        uint32_t sAhi = base;
        uint32_t sAlo = base + FAEL * 2;
        uint32_t sBhi = base + 4 * FAEL;
        uint32_t sBlo = base + 4 * FAEL + FBEL * 2;
#pragma unroll
        for (int ks = 0; ks < BK; ks += 16) {
            uint32_t bh[2][2];
            uint32_t bl[2][2];
            uint32_t offb = (uint32_t)(((wid * 16 + lr) * ASTR + ks + lc) * 2);
            uint32_t r0, r1, r2, r3;
            ldsm_x4(r0, r1, r2, r3, sBhi + offb);
            bh[0][0] = r0;
            bh[0][1] = r2;
            bh[1][0] = r1;
            bh[1][1] = r3;
            ldsm_x4(r0, r1, r2, r3, sBlo + offb);
            bl[0][0] = r0;
            bl[0][1] = r2;
            bl[1][0] = r1;
            bl[1][1] = r3;
            uint32_t a[2][4];
#pragma unroll
            for (int mt = 0; mt < 2; mt++) {
                uint32_t offa = (uint32_t)(((mt * 16 + lr) * ASTR + ks + lc) * 2);
                ldsm_x4(a[mt][0], a[mt][1], a[mt][2], a[mt][3], sAhi + offa);
            }
#pragma unroll
            for (int mt = 0; mt < 2; mt++) {
#pragma unroll
                for (int nt = 0; nt < 2; nt++) {
                    mma_f16(acc[mt][nt], a[mt], bh[nt]);
                    mma_f16(acc[mt][nt], a[mt], bl[nt]);
                }
            }
#pragma unroll
            for (int mt = 0; mt < 2; mt++) {
                uint32_t offa = (uint32_t)(((mt * 16 + lr) * ASTR + ks + lc) * 2);
                ldsm_x4(a[mt][0], a[mt][1], a[mt][2], a[mt][3], sAlo + offa);
            }
#pragma unroll
            for (int mt = 0; mt < 2; mt++) {
#pragma unroll
                for (int nt = 0; nt < 2; nt++) {
                    mma_f16(acc[mt][nt], a[mt], bh[nt]);
                }
            }
        }
        __syncthreads();
    }

    const int g = lane >> 2;
    const int tg2 = (lane & 3) * 2;
    float* P = g_part + (size_t)blockIdx.y * 16384;
#pragma unroll
    for (int mt = 0; mt < 2; mt++) {
        int r = mt * 16 + g;
#pragma unroll
        for (int nt = 0; nt < 2; nt++) {
            int c = col0 + wid * 16 + nt * 8 + tg2;
            float2 o0;
            float2 o1;
            o0.x = acc[mt][nt][0];
            o0.y = acc[mt][nt][1];
            o1.x = acc[mt][nt][2];
            o1.y = acc[mt][nt][3];
            *(float2*)(P + (size_t)r * 512 + c) = o0;
            *(float2*)(P + (size_t)(r + 8) * 512 + c) = o1;
        }
    }
}

/* ------------------------------------------------------------------ */
/* Kernel 6: deterministic split-K reduce + bias. grid 64 x 256.       */
/* ------------------------------------------------------------------ */
__global__ __launch_bounds__(256) void reduce_kernel(float* __restrict__ out,
                                                     const float* __restrict__ bm) {
    const int idx = blockIdx.x * 256 + threadIdx.x; /* == m*512 + n */
    const int n = idx & 511;
    float sum = bm[n];
#pragma unroll 8
    for (int s = 0; s < KSPLIT; s++) {
        sum += g_part[(size_t)s * 16384 + idx];
    }
    out[idx] = sum;
}

/* ------------------------------------------------------------------ */
extern "C" void kernel_launch(void* const* d_in, const int* in_sizes, int n_in,
                              void* d_out, int out_size) {
    const float* x = (const float*)d_in[0];
    const float* Wq = (const float*)d_in[1];
    const float* bq = (const float*)d_in[2];
    const float* Wk = (const float*)d_in[3];
    const float* bk = (const float*)d_in[4];
    const float* Wm = (const float*)d_in[5];
    const float* bm = (const float*)d_in[6];

    float* out = (float*)d_out;   /* [32, 512] */
    float* attn = out + 32 * 512; /* [32, 512, 512] */

    cudaFuncSetAttribute(ax_kernel, cudaFuncAttributeMaxDynamicSharedMemorySize,
                         AXBYTES);
    cudaFuncSetAttribute(final_kernel, cudaFuncAttributeMaxDynamicSharedMemorySize,
                         FBYTES);

    proj_kernel<<<dim3(4, 128, 2), 256>>>(x, Wq, bq, Wk, bk);
    scores_kernel<<<dim3(4, 4, 32), 256>>>(attn);
    softmax_kernel<<<16384, 256>>>(attn);
    ax_kernel<<<dim3(4, 4, 32), 256, AXBYTES>>>(attn, x);
    final_kernel<<<dim3(4, KSPLIT), 256, FBYTES>>>(Wm);
    reduce_kernel<<<64, 256>>>(out, bm);
}

// round 6
// speedup vs baseline: 1.6195x; 1.2679x over previous
#include <cuda_runtime.h>
#include <cuda_fp16.h>
#include <stdint.h>
#include <math.h>

#define ASTR 40            /* padded smem stride in fp16 elems (80B rows) */
#define BK 32
#define NITER 16           /* K=512 / BK */
#define KSPLIT 128
#define KCHUNK 2048

/* Scratch: __device__ globals (allocation-free rule) */
__device__ uint16_t xd16[32 * 512 * 512];   /* x direct fp16 [b*512+n][h] */
__device__ uint16_t wt16[2 * 512 * 512];    /* Wq^T, Wk^T fp16 [z][n][k] */
__device__ uint16_t q16[32 * 512 * 512];    /* q fp16 */
__device__ uint16_t k16[32 * 512 * 512];    /* k fp16 */
__device__ uint16_t at_h[32 * 512 * 512];   /* softmax(attn) fp16 hi/lo */
__device__ uint16_t at_l[32 * 512 * 512];
__device__ uint16_t xt_h[32 * 512 * 512];   /* x^T fp16 hi/lo [b][h][m] */
__device__ uint16_t xt_l[32 * 512 * 512];
__device__ uint16_t axh[32 * 512 * 512];    /* attn@x fp16 hi/lo */
__device__ uint16_t axl[32 * 512 * 512];
__device__ float g_part[KSPLIT * 32 * 512];

/* ------------------------------------------------------------------ */
/* Helpers                                                             */
/* ------------------------------------------------------------------ */
__device__ __forceinline__ uint32_t sptr(const void* p) {
    return (uint32_t)__cvta_generic_to_shared(p);
}

__device__ __forceinline__ void ldsm_x4(uint32_t& r0, uint32_t& r1,
                                        uint32_t& r2, uint32_t& r3,
                                        uint32_t addr) {
    asm volatile("ldmatrix.sync.aligned.m8n8.x4.shared.b16 {%0,%1,%2,%3}, [%4];"
                 : "=r"(r0), "=r"(r1), "=r"(r2), "=r"(r3)
                 : "r"(addr));
}

__device__ __forceinline__ void mma_f16(float* c, const uint32_t* a,
                                        const uint32_t* b) {
    asm volatile(
        "mma.sync.aligned.m16n8k16.row.col.f32.f16.f16.f32 "
        "{%0,%1,%2,%3}, {%4,%5,%6,%7}, {%8,%9}, {%0,%1,%2,%3};"
        : "+f"(c[0]), "+f"(c[1]), "+f"(c[2]), "+f"(c[3])
        : "r"(a[0]), "r"(a[1]), "r"(a[2]), "r"(a[3]),
          "r"(b[0]), "r"(b[1]));
}

__device__ __forceinline__ void cpa16(uint32_t dst, const void* src) {
    asm volatile("cp.async.cg.shared.global [%0], [%1], 16;"
                 :: "r"(dst), "l"(src) : "memory");
}
__device__ __forceinline__ void cpa_commit() {
    asm volatile("cp.async.commit_group;" ::: "memory");
}
template <int N>
__device__ __forceinline__ void cpa_wait() {
    asm volatile("cp.async.wait_group %0;" :: "n"(N) : "memory");
}

__device__ __forceinline__ uint16_t h1(float v) {
    __half h = __float2half_rn(v);
    return *reinterpret_cast<uint16_t*>(&h);
}
__device__ __forceinline__ void split1h(float v, uint16_t& hh, uint16_t& ll) {
    __half hb = __float2half_rn(v);
    hh = *reinterpret_cast<uint16_t*>(&hb);
    __half lb = __float2half_rn(v - __half2float(hb));
    ll = *reinterpret_cast<uint16_t*>(&lb);
}

__device__ __forceinline__ void pack8_plain(const float* v, uint4& u) {
    uint16_t h[8];
#pragma unroll
    for (int j = 0; j < 8; j++) {
        h[j] = h1(v[j]);
    }
    u.x = (uint32_t)h[0] | ((uint32_t)h[1] << 16);
    u.y = (uint32_t)h[2] | ((uint32_t)h[3] << 16);
    u.z = (uint32_t)h[4] | ((uint32_t)h[5] << 16);
    u.w = (uint32_t)h[6] | ((uint32_t)h[7] << 16);
}

__device__ __forceinline__ void pack8_split(const float* v, uint4& uh, uint4& ul) {
    uint16_t h[8], l[8];
#pragma unroll
    for (int j = 0; j < 8; j++) {
        split1h(v[j], h[j], l[j]);
    }
    uh.x = (uint32_t)h[0] | ((uint32_t)h[1] << 16);
    uh.y = (uint32_t)h[2] | ((uint32_t)h[3] << 16);
    uh.z = (uint32_t)h[4] | ((uint32_t)h[5] << 16);
    uh.w = (uint32_t)h[6] | ((uint32_t)h[7] << 16);
    ul.x = (uint32_t)l[0] | ((uint32_t)l[1] << 16);
    ul.y = (uint32_t)l[2] | ((uint32_t)l[3] << 16);
    ul.z = (uint32_t)l[4] | ((uint32_t)l[5] << 16);
    ul.w = (uint32_t)l[6] | ((uint32_t)l[7] << 16);
}

/* copy one 128x32 fp16 tile (src ld=512, pre-offset by k0) into smem  */
__device__ __forceinline__ void cpa_tile(uint32_t sdst, const uint16_t* src,
                                         int tid) {
#pragma unroll
    for (int i = 0; i < 2; i++) {
        int q = i * 256 + tid;
        int row = q >> 2;
        int c = (q & 3) * 8;
        cpa16(sdst + (uint32_t)(row * ASTR + c) * 2, src + (size_t)row * 512 + c);
    }
}

/* ------------------------------------------------------------------ */
/* Compute: one BK=32 slab, 128x128 CTA, plain fp16.                   */
/* ------------------------------------------------------------------ */
__device__ __forceinline__ void compute128_h(uint32_t sA, uint32_t sB,
                                             int wm, int wn, int lane,
                                             float acc[4][4][4]) {
    const int lr = (lane & 7) + ((lane >> 3) & 1) * 8;
    const int lc = (lane >> 4) * 8;
#pragma unroll
    for (int ks = 0; ks < BK; ks += 16) {
        uint32_t b[4][2];
#pragma unroll
        for (int p = 0; p < 2; p++) {
            uint32_t off = (uint32_t)(((wn * 32 + p * 16 + lr) * ASTR + ks + lc) * 2);
            uint32_t r0, r1, r2, r3;
            ldsm_x4(r0, r1, r2, r3, sB + off);
            b[2 * p][0] = r0;
            b[2 * p][1] = r2;
            b[2 * p + 1][0] = r1;
            b[2 * p + 1][1] = r3;
        }
        uint32_t a[4][4];
#pragma unroll
        for (int mt = 0; mt < 4; mt++) {
            uint32_t off = (uint32_t)(((wm * 64 + mt * 16 + lr) * ASTR + ks + lc) * 2);
            ldsm_x4(a[mt][0], a[mt][1], a[mt][2], a[mt][3], sA + off);
        }
#pragma unroll
        for (int mt = 0; mt < 4; mt++) {
#pragma unroll
            for (int nt = 0; nt < 4; nt++) {
                mma_f16(acc[mt][nt], a[mt], b[nt]);
            }
        }
    }
}

/* 3-term hi/lo split variant */
__device__ __forceinline__ void compute128_s(uint32_t sAhi, uint32_t sAlo,
                                             uint32_t sBhi, uint32_t sBlo,
                                             int wm, int wn, int lane,
                                             float acc[4][4][4]) {
    const int lr = (lane & 7) + ((lane >> 3) & 1) * 8;
    const int lc = (lane >> 4) * 8;
#pragma unroll
    for (int ks = 0; ks < BK; ks += 16) {
        uint32_t bh[4][2];
        uint32_t bl[4][2];
#pragma unroll
        for (int p = 0; p < 2; p++) {
            uint32_t off = (uint32_t)(((wn * 32 + p * 16 + lr) * ASTR + ks + lc) * 2);
            uint32_t r0, r1, r2, r3;
            ldsm_x4(r0, r1, r2, r3, sBhi + off);
            bh[2 * p][0] = r0;
            bh[2 * p][1] = r2;
            bh[2 * p + 1][0] = r1;
            bh[2 * p + 1][1] = r3;
            ldsm_x4(r0, r1, r2, r3, sBlo + off);
            bl[2 * p][0] = r0;
            bl[2 * p][1] = r2;
            bl[2 * p + 1][0] = r1;
            bl[2 * p + 1][1] = r3;
        }
        uint32_t a[4][4];
#pragma unroll
        for (int mt = 0; mt < 4; mt++) {
            uint32_t off = (uint32_t)(((wm * 64 + mt * 16 + lr) * ASTR + ks + lc) * 2);
            ldsm_x4(a[mt][0], a[mt][1], a[mt][2], a[mt][3], sAhi + off);
        }
#pragma unroll
        for (int mt = 0; mt < 4; mt++) {
#pragma unroll
            for (int nt = 0; nt < 4; nt++) {
                mma_f16(acc[mt][nt], a[mt], bh[nt]);
                mma_f16(acc[mt][nt], a[mt], bl[nt]);
            }
        }
#pragma unroll
        for (int mt = 0; mt < 4; mt++) {
            uint32_t off = (uint32_t)(((wm * 64 + mt * 16 + lr) * ASTR + ks + lc) * 2);
            ldsm_x4(a[mt][0], a[mt][1], a[mt][2], a[mt][3], sAlo + off);
        }
#pragma unroll
        for (int mt = 0; mt < 4; mt++) {
#pragma unroll
            for (int nt = 0; nt < 4; nt++) {
                mma_f16(acc[mt][nt], a[mt], bh[nt]);
            }
        }
    }
}

/* ------------------------------------------------------------------ */
/* Prep 1: x fp32 -> direct plain fp16. grid 4096 x 256.               */
/* ------------------------------------------------------------------ */
__global__ __launch_bounds__(256) void prep_xd(const float* __restrict__ x) {
    int lin = blockIdx.x * 256 + threadIdx.x;
    size_t e = (size_t)lin * 8;
    float v[8];
    float4 a = *(const float4*)(x + e);
    float4 b = *(const float4*)(x + e + 4);
    v[0] = a.x; v[1] = a.y; v[2] = a.z; v[3] = a.w;
    v[4] = b.x; v[5] = b.y; v[6] = b.z; v[7] = b.w;
    uint4 u;
    pack8_plain(v, u);
    *(uint4*)(xd16 + e) = u;
}

/* ------------------------------------------------------------------ */
/* Prep 2: x -> transposed split fp16 (xt_h/xt_l). grid (8,8,32).      */
/* ------------------------------------------------------------------ */
__global__ __launch_bounds__(256) void prep_xt(const float* __restrict__ x) {
    __shared__ float ts[64][65];
    const int tid = threadIdx.x;
    const int m0 = blockIdx.y * 64;
    const int h0 = blockIdx.x * 64;
    const size_t off = (size_t)blockIdx.z * 262144;
    const float* src = x + off + (size_t)m0 * 512 + h0;

#pragma unroll
    for (int i = 0; i < 4; i++) {
        int lin = i * 256 + tid;
        int r = lin >> 4;
        int c4 = (lin & 15) * 4;
        float4 v = *(const float4*)(src + (size_t)r * 512 + c4);
        ts[r][c4 + 0] = v.x;
        ts[r][c4 + 1] = v.y;
        ts[r][c4 + 2] = v.z;
        ts[r][c4 + 3] = v.w;
    }
    __syncthreads();

#pragma unroll
    for (int i = 0; i < 2; i++) {
        int lin = i * 256 + tid;
        int hr = lin >> 3;
        int m8 = (lin & 7) * 8;
        float v[8];
#pragma unroll
        for (int j = 0; j < 8; j++) {
            v[j] = ts[m8 + j][hr];
        }
        uint4 uh, ul;
        pack8_split(v, uh, ul);
        size_t dst = off + (size_t)(h0 + hr) * 512 + m0 + m8;
        *(uint4*)(xt_h + dst) = uh;
        *(uint4*)(xt_l + dst) = ul;
    }
}

/* ------------------------------------------------------------------ */
/* Prep 3: Wq/Wk -> transposed plain fp16 (wt16). grid (8,8,2).        */
/* ------------------------------------------------------------------ */
__global__ __launch_bounds__(256) void prep_wt(const float* __restrict__ Wq,
                                               const float* __restrict__ Wk) {
    __shared__ float ts[64][65];
    const int tid = threadIdx.x;
    const int k0 = blockIdx.y * 64;
    const int n0 = blockIdx.x * 64;
    const float* src = (blockIdx.z ? Wk : Wq) + (size_t)k0 * 512 + n0;
    const size_t dstoff = (size_t)blockIdx.z * 262144;

#pragma unroll
    for (int i = 0; i < 4; i++) {
        int lin = i * 256 + tid;
        int r = lin >> 4;
        int c4 = (lin & 15) * 4;
        float4 v = *(const float4*)(src + (size_t)r * 512 + c4);
        ts[r][c4 + 0] = v.x;
        ts[r][c4 + 1] = v.y;
        ts[r][c4 + 2] = v.z;
        ts[r][c4 + 3] = v.w;
    }
    __syncthreads();

#pragma unroll
    for (int i = 0; i < 2; i++) {
        int lin = i * 256 + tid;
        int nr = lin >> 3;
        int k8 = (lin & 7) * 8;
        float v[8];
#pragma unroll
        for (int j = 0; j < 8; j++) {
            v[j] = ts[k8 + j][nr];
        }
        uint4 u;
        pack8_plain(v, u);
        *(uint4*)(wt16 + dstoff + (size_t)(n0 + nr) * 512 + k0 + k8) = u;
    }
}

/* ------------------------------------------------------------------ */
/* Kernel: q/k projections. plain fp16, cp.async 2-stage.              */
/* grid (4, 128, 2), 256 thr, 2 CTAs/SM.                               */
/* ------------------------------------------------------------------ */
#define PTILE (128 * ASTR)             /* elems per array */

__global__ __launch_bounds__(256, 2) void proj_kernel(
    const float* __restrict__ bq, const float* __restrict__ bk) {
    __shared__ alignas(16) uint16_t smem[2][2 * PTILE];

    const int tid = threadIdx.x;
    const int lane = tid & 31;
    const int wid = tid >> 5;
    const int wm = wid & 1;
    const int wn = wid >> 1;
    const int z = blockIdx.z;
    const int row0 = blockIdx.y * 128;
    const int col0 = blockIdx.x * 128;

    const uint16_t* A = xd16 + (size_t)row0 * 512;
    const uint16_t* B = wt16 + (size_t)z * 262144 + (size_t)col0 * 512;

    float acc[4][4][4] = {};

    cpa_tile(sptr(smem[0]), A, tid);
    cpa_tile(sptr(smem[0]) + PTILE * 2, B, tid);
    cpa_commit();
    cpa_tile(sptr(smem[1]), A + BK, tid);
    cpa_tile(sptr(smem[1]) + PTILE * 2, B + BK, tid);
    cpa_commit();

    for (int c = 0; c < NITER; c++) {
        if (c == NITER - 1) {
            cpa_wait<0>();
        } else {
            cpa_wait<1>();
        }
        __syncthreads();
        int buf = c & 1;
        compute128_h(sptr(smem[buf]), sptr(smem[buf]) + PTILE * 2, wm, wn, lane, acc);
        __syncthreads();
        if (c + 2 < NITER) {
            int k0 = (c + 2) * BK;
            cpa_tile(sptr(smem[buf]), A + k0, tid);
            cpa_tile(sptr(smem[buf]) + PTILE * 2, B + k0, tid);
            cpa_commit();
        }
    }

    const float* bias = z ? bk : bq;
    uint16_t* O = z ? k16 : q16;
    const int g = lane >> 2;
    const int tg2 = (lane & 3) * 2;
#pragma unroll
    for (int mt = 0; mt < 4; mt++) {
        int r = row0 + wm * 64 + mt * 16 + g;
#pragma unroll
        for (int nt = 0; nt < 4; nt++) {
            int c = col0 + wn * 32 + nt * 8 + tg2;
            float2 bv = *(const float2*)(bias + c);
            __half2 p0 = __floats2half2_rn(acc[mt][nt][0] + bv.x, acc[mt][nt][1] + bv.y);
            __half2 p1 = __floats2half2_rn(acc[mt][nt][2] + bv.x, acc[mt][nt][3] + bv.y);
            *(uint32_t*)(O + (size_t)r * 512 + c) = *reinterpret_cast<uint32_t*>(&p0);
            *(uint32_t*)(O + (size_t)(r + 8) * 512 + c) = *reinterpret_cast<uint32_t*>(&p1);
        }
    }
}

/* ------------------------------------------------------------------ */
/* Kernel: scores = sigmoid(q k^T / sqrt(512)). grid (4,4,32).         */
/* ------------------------------------------------------------------ */
__global__ __launch_bounds__(256, 2) void scores_kernel(float* __restrict__ attn) {
    __shared__ alignas(16) uint16_t smem[2][2 * PTILE];

    const int tid = threadIdx.x;
    const int lane = tid & 31;
    const int wid = tid >> 5;
    const int wm = wid & 1;
    const int wn = wid >> 1;
    const int b = blockIdx.z;
    const int row0 = blockIdx.y * 128;
    const int col0 = blockIdx.x * 128;

    const uint16_t* A = q16 + ((size_t)b * 512 + row0) * 512;
    const uint16_t* B = k16 + ((size_t)b * 512 + col0) * 512;

    float acc[4][4][4] = {};

    cpa_tile(sptr(smem[0]), A, tid);
    cpa_tile(sptr(smem[0]) + PTILE * 2, B, tid);
    cpa_commit();
    cpa_tile(sptr(smem[1]), A + BK, tid);
    cpa_tile(sptr(smem[1]) + PTILE * 2, B + BK, tid);
    cpa_commit();

    for (int c = 0; c < NITER; c++) {
        if (c == NITER - 1) {
            cpa_wait<0>();
        } else {
            cpa_wait<1>();
        }
        __syncthreads();
        int buf = c & 1;
        compute128_h(sptr(smem[buf]), sptr(smem[buf]) + PTILE * 2, wm, wn, lane, acc);
        __syncthreads();
        if (c + 2 < NITER) {
            int k0 = (c + 2) * BK;
            cpa_tile(sptr(smem[buf]), A + k0, tid);
            cpa_tile(sptr(smem[buf]) + PTILE * 2, B + k0, tid);
            cpa_commit();
        }
    }

    const float scale = 0.04419417382415922f; /* 1/sqrt(512) */
    float* S = attn + (size_t)b * 262144;
    const int g = lane >> 2;
    const int tg2 = (lane & 3) * 2;
#pragma unroll
    for (int mt = 0; mt < 4; mt++) {
        int r = row0 + wm * 64 + mt * 16 + g;
#pragma unroll
        for (int nt = 0; nt < 4; nt++) {
            int c = col0 + wn * 32 + nt * 8 + tg2;
            float2 o0;
            float2 o1;
            o0.x = 1.f / (1.f + expf(-acc[mt][nt][0] * scale));
            o0.y = 1.f / (1.f + expf(-acc[mt][nt][1] * scale));
            o1.x = 1.f / (1.f + expf(-acc[mt][nt][2] * scale));
            o1.y = 1.f / (1.f + expf(-acc[mt][nt][3] * scale));
            *(float2*)(S + (size_t)r * 512 + c) = o0;
            *(float2*)(S + (size_t)(r + 8) * 512 + c) = o1;
        }
    }
}

/* ------------------------------------------------------------------ */
/* Kernel: row softmax in-place + fp16 hi/lo copy. grid 16384.         */
/* ------------------------------------------------------------------ */
__global__ __launch_bounds__(256) void softmax_kernel(float* __restrict__ attn) {
    const size_t base = (size_t)blockIdx.x * 512;
    float* p = attn + base;
    const int tid = threadIdx.x;
    float e0 = expf(p[tid]);
    float e1 = expf(p[tid + 256]);
    float s = e0 + e1;
#pragma unroll
    for (int o = 16; o > 0; o >>= 1) {
        s += __shfl_xor_sync(0xffffffffu, s, o);
    }
    __shared__ float ws[8];
    if ((tid & 31) == 0) {
        ws[tid >> 5] = s;
    }
    __syncthreads();
    if (tid < 8) {
        float t = ws[tid];
#pragma unroll
        for (int o = 4; o > 0; o >>= 1) {
            t += __shfl_xor_sync(0xffu, t, o);
        }
        if (tid == 0) {
            ws[0] = t;
        }
    }
    __syncthreads();
    const float inv = 1.f / ws[0];
    float v0 = e0 * inv;
    float v1 = e1 * inv;
    p[tid] = v0;
    p[tid + 256] = v1;
    uint16_t h, l;
    split1h(v0, h, l);
    at_h[base + tid] = h;
    at_l[base + tid] = l;
    split1h(v1, h, l);
    at_h[base + tid + 256] = h;
    at_l[base + tid + 256] = l;
}

/* ------------------------------------------------------------------ */
/* Kernel: ax = attn @ x. fp16 3-term split, cp.async 2-stage,         */
/* dynamic smem (81920 B). grid (4,4,32), 2 CTAs/SM.                   */
/* ------------------------------------------------------------------ */
#define SSE (4 * PTILE)                /* elems per stage */
#define AXBYTES (2 * SSE * 2)          /* 81920 bytes */

__global__ __launch_bounds__(256, 2) void ax_kernel() {
    extern __shared__ uint16_t dsm[];

    const int tid = threadIdx.x;
    const int lane = tid & 31;
    const int wid = tid >> 5;
    const int wm = wid & 1;
    const int wn = wid >> 1;
    const int b = blockIdx.z;
    const int row0 = blockIdx.y * 128;
    const int col0 = blockIdx.x * 128;

    const uint16_t* Ah = at_h + ((size_t)b * 512 + row0) * 512;
    const uint16_t* Al = at_l + ((size_t)b * 512 + row0) * 512;
    const uint16_t* Bh = xt_h + ((size_t)b * 512 + col0) * 512;
    const uint16_t* Bl = xt_l + ((size_t)b * 512 + col0) * 512;

    float acc[4][4][4] = {};

    const uint32_t s0 = sptr(dsm);
#pragma unroll
    for (int st = 0; st < 2; st++) {
        uint32_t sb = s0 + st * SSE * 2;
        int k0 = st * BK;
        cpa_tile(sb, Ah + k0, tid);
        cpa_tile(sb + PTILE * 2, Al + k0, tid);
        cpa_tile(sb + 2 * PTILE * 2, Bh + k0, tid);
        cpa_tile(sb + 3 * PTILE * 2, Bl + k0, tid);
        cpa_commit();
    }

    for (int c = 0; c < NITER; c++) {
        if (c == NITER - 1) {
            cpa_wait<0>();
        } else {
            cpa_wait<1>();
        }
        __syncthreads();
        int buf = c & 1;
        uint32_t sb = s0 + buf * SSE * 2;
        compute128_s(sb, sb + PTILE * 2, sb + 2 * PTILE * 2, sb + 3 * PTILE * 2,
                     wm, wn, lane, acc);
        __syncthreads();
        if (c + 2 < NITER) {
            int k0 = (c + 2) * BK;
            cpa_tile(sb, Ah + k0, tid);
            cpa_tile(sb + PTILE * 2, Al + k0, tid);
            cpa_tile(sb + 2 * PTILE * 2, Bh + k0, tid);
            cpa_tile(sb + 3 * PTILE * 2, Bl + k0, tid);
            cpa_commit();
        }
    }

    const size_t rowg = (size_t)b * 512;
    const int g = lane >> 2;
    const int tg2 = (lane & 3) * 2;
#pragma unroll
    for (int mt = 0; mt < 4; mt++) {
        int r = row0 + wm * 64 + mt * 16 + g;
#pragma unroll
        for (int nt = 0; nt < 4; nt++) {
            int c = col0 + wn * 32 + nt * 8 + tg2;
            uint16_t h0, l0, h1v, l1v;
            split1h(acc[mt][nt][0], h0, l0);
            split1h(acc[mt][nt][1], h1v, l1v);
            *(uint32_t*)(axh + (rowg + r) * 512 + c) = (uint32_t)h0 | ((uint32_t)h1v << 16);
            *(uint32_t*)(axl + (rowg + r) * 512 + c) = (uint32_t)l0 | ((uint32_t)l1v << 16);
            split1h(acc[mt][nt][2], h0, l0);
            split1h(acc[mt][nt][3], h1v, l1v);
            *(uint32_t*)(axh + (rowg + r + 8) * 512 + c) = (uint32_t)h0 | ((uint32_t)h1v << 16);
            *(uint32_t*)(axl + (rowg + r + 8) * 512 + c) = (uint32_t)l0 | ((uint32_t)l1v << 16);
        }
    }
}

/* ------------------------------------------------------------------ */
/* Kernel: split-K partials of out = ax.reshape(32,262144) @ Wm.       */
/* A pre-split fp16, Wm split in-kernel. grid (4, KSPLIT), 2 CTAs/SM.  */
/* ------------------------------------------------------------------ */
#define FAEL (32 * ASTR)
#define FBEL (128 * ASTR)
#define FSTAGE (2 * FAEL + 2 * FBEL)
#define FBYTES (2 * FSTAGE * 2)

__global__ __launch_bounds__(256, 2) void final_kernel(const float* __restrict__ Wm) {
    extern __shared__ uint16_t dsm[];

    const int tid = threadIdx.x;
    const int lane = tid & 31;
    const int wid = tid >> 5;
    const int col0 = blockIdx.x * 128;
    const size_t kbase = (size_t)blockIdx.y * KCHUNK;

    float acc[2][2][4] = {};
    uint2 va_h, va_l;
    float4 vb[4];
    const int am = tid >> 3;
    const int ak = (tid & 7) * 4;

    va_h = *(const uint2*)(axh + (size_t)am * 262144 + kbase + ak);
    va_l = *(const uint2*)(axl + (size_t)am * 262144 + kbase + ak);
#pragma unroll
    for (int i = 0; i < 4; i++) {
        int idx = i * 256 + tid;
        vb[i] = *(const float4*)(Wm + (kbase + (idx >> 5)) * 512 + col0 + (idx & 31) * 4);
    }

    auto store_stage = [&](uint16_t* stg) {
        *(uint2*)(stg + am * ASTR + ak) = va_h;
        *(uint2*)(stg + FAEL + am * ASTR + ak) = va_l;
        uint16_t* bh = stg + 2 * FAEL;
        uint16_t* bl = stg + 2 * FAEL + FBEL;
#pragma unroll
        for (int i = 0; i < 4; i++) {
            int idx = i * 256 + tid;
            int k = idx >> 5;
            int n = (idx & 31) * 4;
            uint16_t hh, ll;
            split1h(vb[i].x, hh, ll);
            bh[(n + 0) * ASTR + k] = hh;
            bl[(n + 0) * ASTR + k] = ll;
            split1h(vb[i].y, hh, ll);
            bh[(n + 1) * ASTR + k] = hh;
            bl[(n + 1) * ASTR + k] = ll;
            split1h(vb[i].z, hh, ll);
            bh[(n + 2) * ASTR + k] = hh;
            bl[(n + 2) * ASTR + k] = ll;
            split1h(vb[i].w, hh, ll);
            bh[(n + 3) * ASTR + k] = hh;
            bl[(n + 3) * ASTR + k] = ll;
        }
    };

    store_stage(dsm);
    va_h = *(const uint2*)(axh + (size_t)am * 262144 + kbase + BK + ak);
    va_l = *(const uint2*)(axl + (size_t)am * 262144 + kbase + BK + ak);
#pragma unroll
    for (int i = 0; i < 4; i++) {
        int idx = i * 256 + tid;
        vb[i] = *(const float4*)(Wm + (kbase + BK + (idx >> 5)) * 512 + col0 + (idx & 31) * 4);
    }
    __syncthreads();

    const int lr = (lane & 7) + ((lane >> 3) & 1) * 8;
    const int lc = (lane >> 4) * 8;

    for (int k0 = 0; k0 < KCHUNK; k0 += BK) {
        int cur = (k0 >> 5) & 1;
        if (k0 + BK < KCHUNK) {
            store_stage(dsm + (cur ^ 1) * FSTAGE);
        }
        if (k0 + 2 * BK < KCHUNK) {
            va_h = *(const uint2*)(axh + (size_t)am * 262144 + kbase + k0 + 2 * BK + ak);
            va_l = *(const uint2*)(axl + (size_t)am * 262144 + kbase + k0 + 2 * BK + ak);
#pragma unroll
            for (int i = 0; i < 4; i++) {
                int idx = i * 256 + tid;
                vb[i] = *(const float4*)(Wm + (kbase + k0 + 2 * BK + (idx >> 5)) * 512 +
                                         col0 + (idx & 31) * 4);
            }
        }
        uint32_t base = sptr(dsm) + cur * FSTAGE * 2;
        uint32_t sAhi = base;
        uint32_t sAlo = base + FAEL * 2;
        uint32_t sBhi = base + 4 * FAEL;
        uint32_t sBlo = base + 4 * FAEL + FBEL * 2;
#pragma unroll
        for (int ks = 0; ks < BK; ks += 16) {
            uint32_t bhf[2][2];
            uint32_t blf[2][2];
            uint32_t offb = (uint32_t)(((wid * 16 + lr) * ASTR + ks + lc) * 2);
            uint32_t r0, r1, r2, r3;
            ldsm_x4(r0, r1, r2, r3, sBhi + offb);
            bhf[0][0] = r0; bhf[0][1] = r2; bhf[1][0] = r1; bhf[1][1] = r3;
            ldsm_x4(r0, r1, r2, r3, sBlo + offb);
            blf[0][0] = r0; blf[0][1] = r2; blf[1][0] = r1; blf[1][1] = r3;
            uint32_t a[2][4];
#pragma unroll
            for (int mt = 0; mt < 2; mt++) {
                uint32_t offa = (uint32_t)(((mt * 16 + lr) * ASTR + ks + lc) * 2);
                ldsm_x4(a[mt][0], a[mt][1], a[mt][2], a[mt][3], sAhi + offa);
            }
#pragma unroll
            for (int mt = 0; mt < 2; mt++) {
#pragma unroll
                for (int nt = 0; nt < 2; nt++) {
                    mma_f16(acc[mt][nt], a[mt], bhf[nt]);
                    mma_f16(acc[mt][nt], a[mt], blf[nt]);
                }
            }
#pragma unroll
            for (int mt = 0; mt < 2; mt++) {
                uint32_t offa = (uint32_t)(((mt * 16 + lr) * ASTR + ks + lc) * 2);
                ldsm_x4(a[mt][0], a[mt][1], a[mt][2], a[mt][3], sAlo + offa);
            }
#pragma unroll
            for (int mt = 0; mt < 2; mt++) {
#pragma unroll
                for (int nt = 0; nt < 2; nt++) {
                    mma_f16(acc[mt][nt], a[mt], bhf[nt]);
                }
            }
        }
        __syncthreads();
    }

    const int g = lane >> 2;
    const int tg2 = (lane & 3) * 2;
    float* P = g_part + (size_t)blockIdx.y * 16384;
#pragma unroll
    for (int mt = 0; mt < 2; mt++) {
        int r = mt * 16 + g;
#pragma unroll
        for (int nt = 0; nt < 2; nt++) {
            int c = col0 + wid * 16 + nt * 8 + tg2;
            float2 o0;
            float2 o1;
            o0.x = acc[mt][nt][0];
            o0.y = acc[mt][nt][1];
            o1.x = acc[mt][nt][2];
            o1.y = acc[mt][nt][3];
            *(float2*)(P + (size_t)r * 512 + c) = o0;
            *(float2*)(P + (size_t)(r + 8) * 512 + c) = o1;
        }
    }
}

/* ------------------------------------------------------------------ */
/* Kernel: deterministic split-K reduce + bias. grid 64 x 256.         */
/* ------------------------------------------------------------------ */
__global__ __launch_bounds__(256) void reduce_kernel(float* __restrict__ out,
                                                     const float* __restrict__ bm) {
    const int idx = blockIdx.x * 256 + threadIdx.x;
    const int n = idx & 511;
    float sum = bm[n];
#pragma unroll 8
    for (int s = 0; s < KSPLIT; s++) {
        sum += g_part[(size_t)s * 16384 + idx];
    }
    out[idx] = sum;
}

/* ------------------------------------------------------------------ */
extern "C" void kernel_launch(void* const* d_in, const int* in_sizes, int n_in,
                              void* d_out, int out_size) {
    const float* x = (const float*)d_in[0];
    const float* Wq = (const float*)d_in[1];
    const float* bq = (const float*)d_in[2];
    const float* Wk = (const float*)d_in[3];
    const float* bk = (const float*)d_in[4];
    const float* Wm = (const float*)d_in[5];
    const float* bm = (const float*)d_in[6];

    float* out = (float*)d_out;   /* [32, 512] */
    float* attn = out + 32 * 512; /* [32, 512, 512] */

    cudaFuncSetAttribute(ax_kernel, cudaFuncAttributeMaxDynamicSharedMemorySize,
                         AXBYTES);
    cudaFuncSetAttribute(final_kernel, cudaFuncAttributeMaxDynamicSharedMemorySize,
                         FBYTES);

    prep_xd<<<4096, 256>>>(x);
    prep_xt<<<dim3(8, 8, 32), 256>>>(x);
    prep_wt<<<dim3(8, 8, 2), 256>>>(Wq, Wk);
    proj_kernel<<<dim3(4, 128, 2), 256>>>(bq, bk);
    scores_kernel<<<dim3(4, 4, 32), 256>>>(attn);
    softmax_kernel<<<16384, 256>>>(attn);
    ax_kernel<<<dim3(4, 4, 32), 256, AXBYTES>>>();
    final_kernel<<<dim3(4, KSPLIT), 256, FBYTES>>>(Wm);
    reduce_kernel<<<64, 256>>>(out, bm);
}

// round 7
// speedup vs baseline: 2.7589x; 1.7036x over previous
#include <cuda_runtime.h>
#include <cuda_fp16.h>
#include <stdint.h>
#include <math.h>

#define ASTR 40            /* padded smem stride in fp16 elems (80B rows) */
#define BK 32
#define NITER 16           /* K=512 / BK */
#define KSPLIT 128
#define KCHUNK 2048

/* Scratch: __device__ globals (allocation-free rule) */
__device__ uint16_t xd16[32 * 512 * 512];   /* x direct fp16 [b*512+n][h] */
__device__ uint16_t xt16[32 * 512 * 512];   /* x^T fp16 [b][h][m] */
__device__ uint16_t wt16[2 * 512 * 512];    /* Wq^T, Wk^T fp16 [z][n][k] */
__device__ uint16_t q16[32 * 512 * 512];    /* q fp16 */
__device__ uint16_t k16[32 * 512 * 512];    /* k fp16 */
__device__ uint16_t at16[32 * 512 * 512];   /* softmax(attn) fp16 */
__device__ uint16_t ax16[32 * 512 * 512];   /* attn@x fp16 */
__device__ float g_part[KSPLIT * 32 * 512];

/* ------------------------------------------------------------------ */
/* Helpers                                                             */
/* ------------------------------------------------------------------ */
__device__ __forceinline__ uint32_t sptr(const void* p) {
    return (uint32_t)__cvta_generic_to_shared(p);
}

__device__ __forceinline__ void ldsm_x4(uint32_t& r0, uint32_t& r1,
                                        uint32_t& r2, uint32_t& r3,
                                        uint32_t addr) {
    asm volatile("ldmatrix.sync.aligned.m8n8.x4.shared.b16 {%0,%1,%2,%3}, [%4];"
                 : "=r"(r0), "=r"(r1), "=r"(r2), "=r"(r3)
                 : "r"(addr));
}

__device__ __forceinline__ void mma_f16(float* c, const uint32_t* a,
                                        const uint32_t* b) {
    asm volatile(
        "mma.sync.aligned.m16n8k16.row.col.f32.f16.f16.f32 "
        "{%0,%1,%2,%3}, {%4,%5,%6,%7}, {%8,%9}, {%0,%1,%2,%3};"
        : "+f"(c[0]), "+f"(c[1]), "+f"(c[2]), "+f"(c[3])
        : "r"(a[0]), "r"(a[1]), "r"(a[2]), "r"(a[3]),
          "r"(b[0]), "r"(b[1]));
}

__device__ __forceinline__ void cpa16(uint32_t dst, const void* src) {
    asm volatile("cp.async.cg.shared.global [%0], [%1], 16;"
                 :: "r"(dst), "l"(src) : "memory");
}
__device__ __forceinline__ void cpa_commit() {
    asm volatile("cp.async.commit_group;" ::: "memory");
}
template <int N>
__device__ __forceinline__ void cpa_wait() {
    asm volatile("cp.async.wait_group %0;" :: "n"(N) : "memory");
}

__device__ __forceinline__ uint16_t h1(float v) {
    __half h = __float2half_rn(v);
    return *reinterpret_cast<uint16_t*>(&h);
}

__device__ __forceinline__ void pack8_plain(const float* v, uint4& u) {
    uint16_t h[8];
#pragma unroll
    for (int j = 0; j < 8; j++) {
        h[j] = h1(v[j]);
    }
    u.x = (uint32_t)h[0] | ((uint32_t)h[1] << 16);
    u.y = (uint32_t)h[2] | ((uint32_t)h[3] << 16);
    u.z = (uint32_t)h[4] | ((uint32_t)h[5] << 16);
    u.w = (uint32_t)h[6] | ((uint32_t)h[7] << 16);
}

/* copy one 128x32 fp16 tile (src ld=512, pre-offset by k0) into smem  */
__device__ __forceinline__ void cpa_tile(uint32_t sdst, const uint16_t* src,
                                         int tid) {
#pragma unroll
    for (int i = 0; i < 2; i++) {
        int q = i * 256 + tid;
        int row = q >> 2;
        int c = (q & 3) * 8;
        cpa16(sdst + (uint32_t)(row * ASTR + c) * 2, src + (size_t)row * 512 + c);
    }
}

/* ------------------------------------------------------------------ */
/* Compute: one BK=32 slab, 128x128 CTA tile, plain fp16. 8 warps.     */
/* ------------------------------------------------------------------ */
__device__ __forceinline__ void compute128_h(uint32_t sA, uint32_t sB,
                                             int wm, int wn, int lane,
                                             float acc[4][4][4]) {
    const int lr = (lane & 7) + ((lane >> 3) & 1) * 8;
    const int lc = (lane >> 4) * 8;
#pragma unroll
    for (int ks = 0; ks < BK; ks += 16) {
        uint32_t b[4][2];
#pragma unroll
        for (int p = 0; p < 2; p++) {
            uint32_t off = (uint32_t)(((wn * 32 + p * 16 + lr) * ASTR + ks + lc) * 2);
            uint32_t r0, r1, r2, r3;
            ldsm_x4(r0, r1, r2, r3, sB + off);
            b[2 * p][0] = r0;
            b[2 * p][1] = r2;
            b[2 * p + 1][0] = r1;
            b[2 * p + 1][1] = r3;
        }
        uint32_t a[4][4];
#pragma unroll
        for (int mt = 0; mt < 4; mt++) {
            uint32_t off = (uint32_t)(((wm * 64 + mt * 16 + lr) * ASTR + ks + lc) * 2);
            ldsm_x4(a[mt][0], a[mt][1], a[mt][2], a[mt][3], sA + off);
        }
#pragma unroll
        for (int mt = 0; mt < 4; mt++) {
#pragma unroll
            for (int nt = 0; nt < 4; nt++) {
                mma_f16(acc[mt][nt], a[mt], b[nt]);
            }
        }
    }
}

/* ------------------------------------------------------------------ */
/* Prep 1: x -> direct fp16 (xd16) AND transposed fp16 (xt16).         */
/* grid (8, 8, 32): 64x64 tiles. Reads x exactly once.                 */
/* ------------------------------------------------------------------ */
__global__ __launch_bounds__(256) void prep_x(const float* __restrict__ x) {
    __shared__ float ts[64][65];
    const int tid = threadIdx.x;
    const int m0 = blockIdx.y * 64;
    const int h0 = blockIdx.x * 64;
    const size_t off = (size_t)blockIdx.z * 262144;
    const float* src = x + off + (size_t)m0 * 512 + h0;

#pragma unroll
    for (int i = 0; i < 4; i++) {
        int lin = i * 256 + tid;
        int r = lin >> 4;
        int c4 = (lin & 15) * 4;
        float4 v = *(const float4*)(src + (size_t)r * 512 + c4);
        ts[r][c4 + 0] = v.x;
        ts[r][c4 + 1] = v.y;
        ts[r][c4 + 2] = v.z;
        ts[r][c4 + 3] = v.w;
    }
    __syncthreads();

#pragma unroll
    for (int i = 0; i < 2; i++) {
        int lin = i * 256 + tid;
        int r = lin >> 3;
        int c8 = (lin & 7) * 8;
        float v[8];
#pragma unroll
        for (int j = 0; j < 8; j++) {
            v[j] = ts[r][c8 + j];
        }
        uint4 u;
        pack8_plain(v, u);
        *(uint4*)(xd16 + off + (size_t)(m0 + r) * 512 + h0 + c8) = u;
    }
#pragma unroll
    for (int i = 0; i < 2; i++) {
        int lin = i * 256 + tid;
        int hr = lin >> 3;
        int m8 = (lin & 7) * 8;
        float v[8];
#pragma unroll
        for (int j = 0; j < 8; j++) {
            v[j] = ts[m8 + j][hr];
        }
        uint4 u;
        pack8_plain(v, u);
        *(uint4*)(xt16 + off + (size_t)(h0 + hr) * 512 + m0 + m8) = u;
    }
}

/* ------------------------------------------------------------------ */
/* Prep 2: Wq/Wk -> transposed plain fp16 (wt16). grid (8,8,2).        */
/* ------------------------------------------------------------------ */
__global__ __launch_bounds__(256) void prep_wt(const float* __restrict__ Wq,
                                               const float* __restrict__ Wk) {
    __shared__ float ts[64][65];
    const int tid = threadIdx.x;
    const int k0 = blockIdx.y * 64;
    const int n0 = blockIdx.x * 64;
    const float* src = (blockIdx.z ? Wk : Wq) + (size_t)k0 * 512 + n0;
    const size_t dstoff = (size_t)blockIdx.z * 262144;

#pragma unroll
    for (int i = 0; i < 4; i++) {
        int lin = i * 256 + tid;
        int r = lin >> 4;
        int c4 = (lin & 15) * 4;
        float4 v = *(const float4*)(src + (size_t)r * 512 + c4);
        ts[r][c4 + 0] = v.x;
        ts[r][c4 + 1] = v.y;
        ts[r][c4 + 2] = v.z;
        ts[r][c4 + 3] = v.w;
    }
    __syncthreads();

#pragma unroll
    for (int i = 0; i < 2; i++) {
        int lin = i * 256 + tid;
        int nr = lin >> 3;
        int k8 = (lin & 7) * 8;
        float v[8];
#pragma unroll
        for (int j = 0; j < 8; j++) {
            v[j] = ts[k8 + j][nr];
        }
        uint4 u;
        pack8_plain(v, u);
        *(uint4*)(wt16 + dstoff + (size_t)(n0 + nr) * 512 + k0 + k8) = u;
    }
}

/* ------------------------------------------------------------------ */
/* Generic plain-fp16 GEMM body: A[128xK] x B^T[128xK] via 2-stage     */
/* cp.async pipeline. Used by proj/scores/ax.                          */
/* ------------------------------------------------------------------ */
#define PTILE (128 * ASTR)

__device__ __forceinline__ void gemm128_body(
    const uint16_t* __restrict__ A, const uint16_t* __restrict__ B,
    uint16_t (*smem)[2 * PTILE], int tid, int wm, int wn, int lane,
    float acc[4][4][4]) {
    cpa_tile(sptr(smem[0]), A, tid);
    cpa_tile(sptr(smem[0]) + PTILE * 2, B, tid);
    cpa_commit();
    cpa_tile(sptr(smem[1]), A + BK, tid);
    cpa_tile(sptr(smem[1]) + PTILE * 2, B + BK, tid);
    cpa_commit();

    for (int c = 0; c < NITER; c++) {
        if (c == NITER - 1) {
            cpa_wait<0>();
        } else {
            cpa_wait<1>();
        }
        __syncthreads();
        int buf = c & 1;
        compute128_h(sptr(smem[buf]), sptr(smem[buf]) + PTILE * 2, wm, wn, lane, acc);
        __syncthreads();
        if (c + 2 < NITER) {
            int k0 = (c + 2) * BK;
            cpa_tile(sptr(smem[buf]), A + k0, tid);
            cpa_tile(sptr(smem[buf]) + PTILE * 2, B + k0, tid);
            cpa_commit();
        }
    }
}

/* ------------------------------------------------------------------ */
/* Kernel: q/k projections. grid (4, 128, 2), 2 CTAs/SM.               */
/* ------------------------------------------------------------------ */
__global__ __launch_bounds__(256, 2) void proj_kernel(
    const float* __restrict__ bq, const float* __restrict__ bk) {
    __shared__ alignas(16) uint16_t smem[2][2 * PTILE];

    const int tid = threadIdx.x;
    const int lane = tid & 31;
    const int wid = tid >> 5;
    const int wm = wid & 1;
    const int wn = wid >> 1;
    const int z = blockIdx.z;
    const int row0 = blockIdx.y * 128;
    const int col0 = blockIdx.x * 128;

    const uint16_t* A = xd16 + (size_t)row0 * 512;
    const uint16_t* B = wt16 + (size_t)z * 262144 + (size_t)col0 * 512;

    float acc[4][4][4] = {};
    gemm128_body(A, B, smem, tid, wm, wn, lane, acc);

    const float* bias = z ? bk : bq;
    uint16_t* O = z ? k16 : q16;
    const int g = lane >> 2;
    const int tg2 = (lane & 3) * 2;
#pragma unroll
    for (int mt = 0; mt < 4; mt++) {
        int r = row0 + wm * 64 + mt * 16 + g;
#pragma unroll
        for (int nt = 0; nt < 4; nt++) {
            int c = col0 + wn * 32 + nt * 8 + tg2;
            float2 bv = *(const float2*)(bias + c);
            __half2 p0 = __floats2half2_rn(acc[mt][nt][0] + bv.x, acc[mt][nt][1] + bv.y);
            __half2 p1 = __floats2half2_rn(acc[mt][nt][2] + bv.x, acc[mt][nt][3] + bv.y);
            *(uint32_t*)(O + (size_t)r * 512 + c) = *reinterpret_cast<uint32_t*>(&p0);
            *(uint32_t*)(O + (size_t)(r + 8) * 512 + c) = *reinterpret_cast<uint32_t*>(&p1);
        }
    }
}

/* ------------------------------------------------------------------ */
/* Kernel: scores = sigmoid(q k^T / sqrt(512)). grid (4,4,32).         */
/* ------------------------------------------------------------------ */
__global__ __launch_bounds__(256, 2) void scores_kernel(float* __restrict__ attn) {
    __shared__ alignas(16) uint16_t smem[2][2 * PTILE];

    const int tid = threadIdx.x;
    const int lane = tid & 31;
    const int wid = tid >> 5;
    const int wm = wid & 1;
    const int wn = wid >> 1;
    const int b = blockIdx.z;
    const int row0 = blockIdx.y * 128;
    const int col0 = blockIdx.x * 128;

    const uint16_t* A = q16 + ((size_t)b * 512 + row0) * 512;
    const uint16_t* B = k16 + ((size_t)b * 512 + col0) * 512;

    float acc[4][4][4] = {};
    gemm128_body(A, B, smem, tid, wm, wn, lane, acc);

    const float scale = 0.04419417382415922f; /* 1/sqrt(512) */
    float* S = attn + (size_t)b * 262144;
    const int g = lane >> 2;
    const int tg2 = (lane & 3) * 2;
#pragma unroll
    for (int mt = 0; mt < 4; mt++) {
        int r = row0 + wm * 64 + mt * 16 + g;
#pragma unroll
        for (int nt = 0; nt < 4; nt++) {
            int c = col0 + wn * 32 + nt * 8 + tg2;
            float2 o0;
            float2 o1;
            o0.x = 1.f / (1.f + expf(-acc[mt][nt][0] * scale));
            o0.y = 1.f / (1.f + expf(-acc[mt][nt][1] * scale));
            o1.x = 1.f / (1.f + expf(-acc[mt][nt][2] * scale));
            o1.y = 1.f / (1.f + expf(-acc[mt][nt][3] * scale));
            *(float2*)(S + (size_t)r * 512 + c) = o0;
            *(float2*)(S + (size_t)(r + 8) * 512 + c) = o1;
        }
    }
}

/* ------------------------------------------------------------------ */
/* Kernel: row softmax in-place + fp16 copy. grid 16384.               */
/* ------------------------------------------------------------------ */
__global__ __launch_bounds__(256) void softmax_kernel(float* __restrict__ attn) {
    const size_t base = (size_t)blockIdx.x * 512;
    float* p = attn + base;
    const int tid = threadIdx.x;
    float e0 = expf(p[tid]);
    float e1 = expf(p[tid + 256]);
    float s = e0 + e1;
#pragma unroll
    for (int o = 16; o > 0; o >>= 1) {
        s += __shfl_xor_sync(0xffffffffu, s, o);
    }
    __shared__ float ws[8];
    if ((tid & 31) == 0) {
        ws[tid >> 5] = s;
    }
    __syncthreads();
    if (tid < 8) {
        float t = ws[tid];
#pragma unroll
        for (int o = 4; o > 0; o >>= 1) {
            t += __shfl_xor_sync(0xffu, t, o);
        }
        if (tid == 0) {
            ws[0] = t;
        }
    }
    __syncthreads();
    const float inv = 1.f / ws[0];
    float v0 = e0 * inv;
    float v1 = e1 * inv;
    p[tid] = v0;
    p[tid + 256] = v1;
    at16[base + tid] = h1(v0);
    at16[base + tid + 256] = h1(v1);
}

/* ------------------------------------------------------------------ */
/* Kernel: ax = attn @ x (plain fp16). grid (4,4,32), 2 CTAs/SM.       */
/* Output fp16 (consumed by final).                                    */
/* ------------------------------------------------------------------ */
__global__ __launch_bounds__(256, 2) void ax_kernel() {
    __shared__ alignas(16) uint16_t smem[2][2 * PTILE];

    const int tid = threadIdx.x;
    const int lane = tid & 31;
    const int wid = tid >> 5;
    const int wm = wid & 1;
    const int wn = wid >> 1;
    const int b = blockIdx.z;
    const int row0 = blockIdx.y * 128;
    const int col0 = blockIdx.x * 128;

    const uint16_t* A = at16 + ((size_t)b * 512 + row0) * 512;
    const uint16_t* B = xt16 + ((size_t)b * 512 + col0) * 512;

    float acc[4][4][4] = {};
    gemm128_body(A, B, smem, tid, wm, wn, lane, acc);

    const size_t rowg = (size_t)b * 512;
    const int g = lane >> 2;
    const int tg2 = (lane & 3) * 2;
#pragma unroll
    for (int mt = 0; mt < 4; mt++) {
        int r = row0 + wm * 64 + mt * 16 + g;
#pragma unroll
        for (int nt = 0; nt < 4; nt++) {
            int c = col0 + wn * 32 + nt * 8 + tg2;
            __half2 p0 = __floats2half2_rn(acc[mt][nt][0], acc[mt][nt][1]);
            __half2 p1 = __floats2half2_rn(acc[mt][nt][2], acc[mt][nt][3]);
            *(uint32_t*)(ax16 + (rowg + r) * 512 + c) = *reinterpret_cast<uint32_t*>(&p0);
            *(uint32_t*)(ax16 + (rowg + r + 8) * 512 + c) = *reinterpret_cast<uint32_t*>(&p1);
        }
    }
}

/* ------------------------------------------------------------------ */
/* Kernel: split-K partials of out = ax.reshape(32,262144) @ Wm.       */
/* Plain fp16; A pre-converted, Wm converted in-kernel.                */
/* grid (4, KSPLIT), 2 CTAs/SM.                                        */
/* ------------------------------------------------------------------ */
#define FAEL (32 * ASTR)
#define FBEL (128 * ASTR)
#define FSTAGE (FAEL + FBEL)

__global__ __launch_bounds__(256, 2) void final_kernel(const float* __restrict__ Wm) {
    __shared__ alignas(16) uint16_t dsm[2 * FSTAGE];

    const int tid = threadIdx.x;
    const int lane = tid & 31;
    const int wid = tid >> 5;
    const int col0 = blockIdx.x * 128;
    const size_t kbase = (size_t)blockIdx.y * KCHUNK;

    float acc[2][2][4] = {};
    uint2 va;
    float4 vb[4];
    const int am = tid >> 3;
    const int ak = (tid & 7) * 4;

    va = *(const uint2*)(ax16 + (size_t)am * 262144 + kbase + ak);
#pragma unroll
    for (int i = 0; i < 4; i++) {
        int idx = i * 256 + tid;
        vb[i] = *(const float4*)(Wm + (kbase + (idx >> 5)) * 512 + col0 + (idx & 31) * 4);
    }

    auto store_stage = [&](uint16_t* stg) {
        *(uint2*)(stg + am * ASTR + ak) = va;
        uint16_t* bh = stg + FAEL;
#pragma unroll
        for (int i = 0; i < 4; i++) {
            int idx = i * 256 + tid;
            int k = idx >> 5;
            int n = (idx & 31) * 4;
            bh[(n + 0) * ASTR + k] = h1(vb[i].x);
            bh[(n + 1) * ASTR + k] = h1(vb[i].y);
            bh[(n + 2) * ASTR + k] = h1(vb[i].z);
            bh[(n + 3) * ASTR + k] = h1(vb[i].w);
        }
    };

    store_stage(dsm);
    va = *(const uint2*)(ax16 + (size_t)am * 262144 + kbase + BK + ak);
#pragma unroll
    for (int i = 0; i < 4; i++) {
        int idx = i * 256 + tid;
        vb[i] = *(const float4*)(Wm + (kbase + BK + (idx >> 5)) * 512 + col0 + (idx & 31) * 4);
    }
    __syncthreads();

    const int lr = (lane & 7) + ((lane >> 3) & 1) * 8;
    const int lc = (lane >> 4) * 8;

    for (int k0 = 0; k0 < KCHUNK; k0 += BK) {
        int cur = (k0 >> 5) & 1;
        if (k0 + BK < KCHUNK) {
            store_stage(dsm + (cur ^ 1) * FSTAGE);
        }
        if (k0 + 2 * BK < KCHUNK) {
            va = *(const uint2*)(ax16 + (size_t)am * 262144 + kbase + k0 + 2 * BK + ak);
#pragma unroll
            for (int i = 0; i < 4; i++) {
                int idx = i * 256 + tid;
                vb[i] = *(const float4*)(Wm + (kbase + k0 + 2 * BK + (idx >> 5)) * 512 +
                                         col0 + (idx & 31) * 4);
            }
        }
        uint32_t base = sptr(dsm) + cur * FSTAGE * 2;
        uint32_t sA = base;
        uint32_t sB = base + FAEL * 2;
#pragma unroll
        for (int ks = 0; ks < BK; ks += 16) {
            uint32_t bf[2][2];
            uint32_t offb = (uint32_t)(((wid * 16 + lr) * ASTR + ks + lc) * 2);
            uint32_t r0, r1, r2, r3;
            ldsm_x4(r0, r1, r2, r3, sB + offb);
            bf[0][0] = r0;
            bf[0][1] = r2;
            bf[1][0] = r1;
            bf[1][1] = r3;
            uint32_t a[2][4];
#pragma unroll
            for (int mt = 0; mt < 2; mt++) {
                uint32_t offa = (uint32_t)(((mt * 16 + lr) * ASTR + ks + lc) * 2);
                ldsm_x4(a[mt][0], a[mt][1], a[mt][2], a[mt][3], sA + offa);
            }
#pragma unroll
            for (int mt = 0; mt < 2; mt++) {
#pragma unroll
                for (int nt = 0; nt < 2; nt++) {
                    mma_f16(acc[mt][nt], a[mt], bf[nt]);
                }
            }
        }
        __syncthreads();
    }

    const int g = lane >> 2;
    const int tg2 = (lane & 3) * 2;
    float* P = g_part + (size_t)blockIdx.y * 16384;
#pragma unroll
    for (int mt = 0; mt < 2; mt++) {
        int r = mt * 16 + g;
#pragma unroll
        for (int nt = 0; nt < 2; nt++) {
            int c = col0 + wid * 16 + nt * 8 + tg2;
            float2 o0;
            float2 o1;
            o0.x = acc[mt][nt][0];
            o0.y = acc[mt][nt][1];
            o1.x = acc[mt][nt][2];
            o1.y = acc[mt][nt][3];
            *(float2*)(P + (size_t)r * 512 + c) = o0;
            *(float2*)(P + (size_t)(r + 8) * 512 + c) = o1;
        }
    }
}

/* ------------------------------------------------------------------ */
/* Kernel: deterministic split-K reduce + bias. grid 64 x 256.         */
/* ------------------------------------------------------------------ */
__global__ __launch_bounds__(256) void reduce_kernel(float* __restrict__ out,
                                                     const float* __restrict__ bm) {
    const int idx = blockIdx.x * 256 + threadIdx.x;
    const int n = idx & 511;
    float sum = bm[n];
#pragma unroll 8
    for (int s = 0; s < KSPLIT; s++) {
        sum += g_part[(size_t)s * 16384 + idx];
    }
    out[idx] = sum;
}

/* ------------------------------------------------------------------ */
extern "C" void kernel_launch(void* const* d_in, const int* in_sizes, int n_in,
                              void* d_out, int out_size) {
    const float* x = (const float*)d_in[0];
    const float* Wq = (const float*)d_in[1];
    const float* bq = (const float*)d_in[2];
    const float* Wk = (const float*)d_in[3];
    const float* bk = (const float*)d_in[4];
    const float* Wm = (const float*)d_in[5];
    const float* bm = (const float*)d_in[6];

    float* out = (float*)d_out;   /* [32, 512] */
    float* attn = out + 32 * 512; /* [32, 512, 512] */

    prep_x<<<dim3(8, 8, 32), 256>>>(x);
    prep_wt<<<dim3(8, 8, 2), 256>>>(Wq, Wk);
    proj_kernel<<<dim3(4, 128, 2), 256>>>(bq, bk);
    scores_kernel<<<dim3(4, 4, 32), 256>>>(attn);
    softmax_kernel<<<16384, 256>>>(attn);
    ax_kernel<<<dim3(4, 4, 32), 256>>>();
    final_kernel<<<dim3(4, KSPLIT), 256>>>(Wm);
    reduce_kernel<<<64, 256>>>(out, bm);
}

// round 8
// speedup vs baseline: 2.8262x; 1.0244x over previous
#include <cuda_runtime.h>
#include <cuda_fp16.h>
#include <stdint.h>
#include <math.h>

#define ASTR 40            /* padded smem stride in fp16 elems (80B rows) */
#define BK 32
#define NITER 16           /* K=512 / BK */
#define STAGES 4
#define KSPLIT 64
#define KCHUNK 4096

/* Scratch: __device__ globals (allocation-free rule) */
__device__ uint16_t xd16[32 * 512 * 512];   /* x direct fp16 [b*512+n][h] */
__device__ uint16_t xt16[32 * 512 * 512];   /* x^T fp16 [b][h][m] */
__device__ uint16_t wt16[2 * 512 * 512];    /* Wq^T, Wk^T fp16 [z][n][k] */
__device__ uint16_t q16[32 * 512 * 512];    /* q fp16 */
__device__ uint16_t k16[32 * 512 * 512];    /* k fp16 */
__device__ uint16_t at16[32 * 512 * 512];   /* softmax(attn) fp16 */
__device__ uint16_t ax16[32 * 512 * 512];   /* attn@x fp16 */
__device__ float g_part[KSPLIT * 32 * 512];

/* ------------------------------------------------------------------ */
/* Helpers                                                             */
/* ------------------------------------------------------------------ */
__device__ __forceinline__ uint32_t sptr(const void* p) {
    return (uint32_t)__cvta_generic_to_shared(p);
}

__device__ __forceinline__ void ldsm_x4(uint32_t& r0, uint32_t& r1,
                                        uint32_t& r2, uint32_t& r3,
                                        uint32_t addr) {
    asm volatile("ldmatrix.sync.aligned.m8n8.x4.shared.b16 {%0,%1,%2,%3}, [%4];"
                 : "=r"(r0), "=r"(r1), "=r"(r2), "=r"(r3)
                 : "r"(addr));
}

__device__ __forceinline__ void mma_f16(float* c, const uint32_t* a,
                                        const uint32_t* b) {
    asm volatile(
        "mma.sync.aligned.m16n8k16.row.col.f32.f16.f16.f32 "
        "{%0,%1,%2,%3}, {%4,%5,%6,%7}, {%8,%9}, {%0,%1,%2,%3};"
        : "+f"(c[0]), "+f"(c[1]), "+f"(c[2]), "+f"(c[3])
        : "r"(a[0]), "r"(a[1]), "r"(a[2]), "r"(a[3]),
          "r"(b[0]), "r"(b[1]));
}

__device__ __forceinline__ void cpa16(uint32_t dst, const void* src) {
    asm volatile("cp.async.cg.shared.global [%0], [%1], 16;"
                 :: "r"(dst), "l"(src) : "memory");
}
__device__ __forceinline__ void cpa_commit() {
    asm volatile("cp.async.commit_group;" ::: "memory");
}
template <int N>
__device__ __forceinline__ void cpa_wait() {
    asm volatile("cp.async.wait_group %0;" :: "n"(N) : "memory");
}

__device__ __forceinline__ uint16_t h1(float v) {
    __half h = __float2half_rn(v);
    return *reinterpret_cast<uint16_t*>(&h);
}

__device__ __forceinline__ void pack8_plain(const float* v, uint4& u) {
    uint16_t h[8];
#pragma unroll
    for (int j = 0; j < 8; j++) {
        h[j] = h1(v[j]);
    }
    u.x = (uint32_t)h[0] | ((uint32_t)h[1] << 16);
    u.y = (uint32_t)h[2] | ((uint32_t)h[3] << 16);
    u.z = (uint32_t)h[4] | ((uint32_t)h[5] << 16);
    u.w = (uint32_t)h[6] | ((uint32_t)h[7] << 16);
}

/* copy one 128x32 fp16 tile (src ld=512, pre-offset by k0) into smem  */
__device__ __forceinline__ void cpa_tile(uint32_t sdst, const uint16_t* src,
                                         int tid) {
#pragma unroll
    for (int i = 0; i < 2; i++) {
        int q = i * 256 + tid;
        int row = q >> 2;
        int c = (q & 3) * 8;
        cpa16(sdst + (uint32_t)(row * ASTR + c) * 2, src + (size_t)row * 512 + c);
    }
}

/* ------------------------------------------------------------------ */
/* Compute: one BK=32 slab, 128x128 CTA tile, plain fp16. 8 warps.     */
/* ------------------------------------------------------------------ */
__device__ __forceinline__ void compute128_h(uint32_t sA, uint32_t sB,
                                             int wm, int wn, int lane,
                                             float acc[4][4][4]) {
    const int lr = (lane & 7) + ((lane >> 3) & 1) * 8;
    const int lc = (lane >> 4) * 8;
#pragma unroll
    for (int ks = 0; ks < BK; ks += 16) {
        uint32_t b[4][2];
#pragma unroll
        for (int p = 0; p < 2; p++) {
            uint32_t off = (uint32_t)(((wn * 32 + p * 16 + lr) * ASTR + ks + lc) * 2);
            uint32_t r0, r1, r2, r3;
            ldsm_x4(r0, r1, r2, r3, sB + off);
            b[2 * p][0] = r0;
            b[2 * p][1] = r2;
            b[2 * p + 1][0] = r1;
            b[2 * p + 1][1] = r3;
        }
        uint32_t a[4][4];
#pragma unroll
        for (int mt = 0; mt < 4; mt++) {
            uint32_t off = (uint32_t)(((wm * 64 + mt * 16 + lr) * ASTR + ks + lc) * 2);
            ldsm_x4(a[mt][0], a[mt][1], a[mt][2], a[mt][3], sA + off);
        }
#pragma unroll
        for (int mt = 0; mt < 4; mt++) {
#pragma unroll
            for (int nt = 0; nt < 4; nt++) {
                mma_f16(acc[mt][nt], a[mt], b[nt]);
            }
        }
    }
}

/* ------------------------------------------------------------------ */
/* Prep 1: x -> direct fp16 (xd16) AND transposed fp16 (xt16).         */
/* ------------------------------------------------------------------ */
__global__ __launch_bounds__(256) void prep_x(const float* __restrict__ x) {
    __shared__ float ts[64][65];
    const int tid = threadIdx.x;
    const int m0 = blockIdx.y * 64;
    const int h0 = blockIdx.x * 64;
    const size_t off = (size_t)blockIdx.z * 262144;
    const float* src = x + off + (size_t)m0 * 512 + h0;

#pragma unroll
    for (int i = 0; i < 4; i++) {
        int lin = i * 256 + tid;
        int r = lin >> 4;
        int c4 = (lin & 15) * 4;
        float4 v = *(const float4*)(src + (size_t)r * 512 + c4);
        ts[r][c4 + 0] = v.x;
        ts[r][c4 + 1] = v.y;
        ts[r][c4 + 2] = v.z;
        ts[r][c4 + 3] = v.w;
    }
    __syncthreads();

#pragma unroll
    for (int i = 0; i < 2; i++) {
        int lin = i * 256 + tid;
        int r = lin >> 3;
        int c8 = (lin & 7) * 8;
        float v[8];
#pragma unroll
        for (int j = 0; j < 8; j++) {
            v[j] = ts[r][c8 + j];
        }
        uint4 u;
        pack8_plain(v, u);
        *(uint4*)(xd16 + off + (size_t)(m0 + r) * 512 + h0 + c8) = u;
    }
#pragma unroll
    for (int i = 0; i < 2; i++) {
        int lin = i * 256 + tid;
        int hr = lin >> 3;
        int m8 = (lin & 7) * 8;
        float v[8];
#pragma unroll
        for (int j = 0; j < 8; j++) {
            v[j] = ts[m8 + j][hr];
        }
        uint4 u;
        pack8_plain(v, u);
        *(uint4*)(xt16 + off + (size_t)(h0 + hr) * 512 + m0 + m8) = u;
    }
}

/* ------------------------------------------------------------------ */
/* Prep 2: Wq/Wk -> transposed plain fp16 (wt16). grid (8,8,2).        */
/* ------------------------------------------------------------------ */
__global__ __launch_bounds__(256) void prep_wt(const float* __restrict__ Wq,
                                               const float* __restrict__ Wk) {
    __shared__ float ts[64][65];
    const int tid = threadIdx.x;
    const int k0 = blockIdx.y * 64;
    const int n0 = blockIdx.x * 64;
    const float* src = (blockIdx.z ? Wk : Wq) + (size_t)k0 * 512 + n0;
    const size_t dstoff = (size_t)blockIdx.z * 262144;

#pragma unroll
    for (int i = 0; i < 4; i++) {
        int lin = i * 256 + tid;
        int r = lin >> 4;
        int c4 = (lin & 15) * 4;
        float4 v = *(const float4*)(src + (size_t)r * 512 + c4);
        ts[r][c4 + 0] = v.x;
        ts[r][c4 + 1] = v.y;
        ts[r][c4 + 2] = v.z;
        ts[r][c4 + 3] = v.w;
    }
    __syncthreads();

#pragma unroll
    for (int i = 0; i < 2; i++) {
        int lin = i * 256 + tid;
        int nr = lin >> 3;
        int k8 = (lin & 7) * 8;
        float v[8];
#pragma unroll
        for (int j = 0; j < 8; j++) {
            v[j] = ts[k8 + j][nr];
        }
        uint4 u;
        pack8_plain(v, u);
        *(uint4*)(wt16 + dstoff + (size_t)(n0 + nr) * 512 + k0 + k8) = u;
    }
}

/* ------------------------------------------------------------------ */
/* Generic plain-fp16 GEMM body: 4-stage cp.async pipeline, one        */
/* __syncthreads per slab. smem layout: stage s at s*(2*PTILE) elems.  */
/* ------------------------------------------------------------------ */
#define PTILE (128 * ASTR)
#define STAGE_BYTES (2 * PTILE * 2)
#define GSMEM_BYTES (STAGES * STAGE_BYTES)   /* 81920 */

__device__ __forceinline__ void gemm128_body(
    const uint16_t* __restrict__ A, const uint16_t* __restrict__ B,
    uint32_t s0, int tid, int wm, int wn, int lane, float acc[4][4][4]) {
#pragma unroll
    for (int s = 0; s < STAGES - 1; s++) {
        uint32_t sb = s0 + s * STAGE_BYTES;
        cpa_tile(sb, A + s * BK, tid);
        cpa_tile(sb + PTILE * 2, B + s * BK, tid);
        cpa_commit();
    }

    for (int c = 0; c < NITER; c++) {
        cpa_wait<STAGES - 2>();
        __syncthreads();
        int nf = c + STAGES - 1;
        if (nf < NITER) {
            uint32_t sb = s0 + (nf & (STAGES - 1)) * STAGE_BYTES;
            cpa_tile(sb, A + nf * BK, tid);
            cpa_tile(sb + PTILE * 2, B + nf * BK, tid);
        }
        cpa_commit();   /* unconditional: keeps group count in lockstep */
        uint32_t sb = s0 + (c & (STAGES - 1)) * STAGE_BYTES;
        compute128_h(sb, sb + PTILE * 2, wm, wn, lane, acc);
    }
}

/* ------------------------------------------------------------------ */
/* Kernel: q/k projections. grid (4, 128, 2), dyn smem, 2 CTAs/SM.     */
/* ------------------------------------------------------------------ */
__global__ __launch_bounds__(256, 2) void proj_kernel(
    const float* __restrict__ bq, const float* __restrict__ bk) {
    extern __shared__ uint16_t dynsm[];

    const int tid = threadIdx.x;
    const int lane = tid & 31;
    const int wid = tid >> 5;
    const int wm = wid & 1;
    const int wn = wid >> 1;
    const int z = blockIdx.z;
    const int row0 = blockIdx.y * 128;
    const int col0 = blockIdx.x * 128;

    const uint16_t* A = xd16 + (size_t)row0 * 512;
    const uint16_t* B = wt16 + (size_t)z * 262144 + (size_t)col0 * 512;

    float acc[4][4][4] = {};
    gemm128_body(A, B, sptr(dynsm), tid, wm, wn, lane, acc);

    const float* bias = z ? bk : bq;
    uint16_t* O = z ? k16 : q16;
    const int g = lane >> 2;
    const int tg2 = (lane & 3) * 2;
#pragma unroll
    for (int mt = 0; mt < 4; mt++) {
        int r = row0 + wm * 64 + mt * 16 + g;
#pragma unroll
        for (int nt = 0; nt < 4; nt++) {
            int c = col0 + wn * 32 + nt * 8 + tg2;
            float2 bv = *(const float2*)(bias + c);
            __half2 p0 = __floats2half2_rn(acc[mt][nt][0] + bv.x, acc[mt][nt][1] + bv.y);
            __half2 p1 = __floats2half2_rn(acc[mt][nt][2] + bv.x, acc[mt][nt][3] + bv.y);
            *(uint32_t*)(O + (size_t)r * 512 + c) = *reinterpret_cast<uint32_t*>(&p0);
            *(uint32_t*)(O + (size_t)(r + 8) * 512 + c) = *reinterpret_cast<uint32_t*>(&p1);
        }
    }
}

/* ------------------------------------------------------------------ */
/* Kernel: scores = sigmoid(q k^T / sqrt(512)). grid (4,4,32).         */
/* ------------------------------------------------------------------ */
__global__ __launch_bounds__(256, 2) void scores_kernel(float* __restrict__ attn) {
    extern __shared__ uint16_t dynsm[];

    const int tid = threadIdx.x;
    const int lane = tid & 31;
    const int wid = tid >> 5;
    const int wm = wid & 1;
    const int wn = wid >> 1;
    const int b = blockIdx.z;
    const int row0 = blockIdx.y * 128;
    const int col0 = blockIdx.x * 128;

    const uint16_t* A = q16 + ((size_t)b * 512 + row0) * 512;
    const uint16_t* B = k16 + ((size_t)b * 512 + col0) * 512;

    float acc[4][4][4] = {};
    gemm128_body(A, B, sptr(dynsm), tid, wm, wn, lane, acc);

    const float scale = 0.04419417382415922f; /* 1/sqrt(512) */
    float* S = attn + (size_t)b * 262144;
    const int g = lane >> 2;
    const int tg2 = (lane & 3) * 2;
#pragma unroll
    for (int mt = 0; mt < 4; mt++) {
        int r = row0 + wm * 64 + mt * 16 + g;
#pragma unroll
        for (int nt = 0; nt < 4; nt++) {
            int c = col0 + wn * 32 + nt * 8 + tg2;
            float2 o0;
            float2 o1;
            o0.x = 1.f / (1.f + expf(-acc[mt][nt][0] * scale));
            o0.y = 1.f / (1.f + expf(-acc[mt][nt][1] * scale));
            o1.x = 1.f / (1.f + expf(-acc[mt][nt][2] * scale));
            o1.y = 1.f / (1.f + expf(-acc[mt][nt][3] * scale));
            *(float2*)(S + (size_t)r * 512 + c) = o0;
            *(float2*)(S + (size_t)(r + 8) * 512 + c) = o1;
        }
    }
}

/* ------------------------------------------------------------------ */
/* Kernel: warp-per-row softmax in-place + fp16 copy. grid 2048.       */
/* Each warp owns one full 512-wide row; shfl-only reduction.          */
/* ------------------------------------------------------------------ */
__global__ __launch_bounds__(256) void softmax_kernel(float* __restrict__ attn) {
    const int w = threadIdx.x >> 5;
    const int lane = threadIdx.x & 31;
    const size_t base = ((size_t)blockIdx.x * 8 + w) * 512;
    float* p = attn + base;

    float4 v[4];
#pragma unroll
    for (int i = 0; i < 4; i++) {
        v[i] = *(const float4*)(p + i * 128 + lane * 4);
    }
    float e[16];
    float s = 0.f;
#pragma unroll
    for (int i = 0; i < 4; i++) {
        e[i * 4 + 0] = expf(v[i].x);
        e[i * 4 + 1] = expf(v[i].y);
        e[i * 4 + 2] = expf(v[i].z);
        e[i * 4 + 3] = expf(v[i].w);
        s += e[i * 4 + 0] + e[i * 4 + 1] + e[i * 4 + 2] + e[i * 4 + 3];
    }
#pragma unroll
    for (int o = 16; o > 0; o >>= 1) {
        s += __shfl_xor_sync(0xffffffffu, s, o);
    }
    const float inv = 1.f / s;
#pragma unroll
    for (int i = 0; i < 4; i++) {
        float4 o;
        o.x = e[i * 4 + 0] * inv;
        o.y = e[i * 4 + 1] * inv;
        o.z = e[i * 4 + 2] * inv;
        o.w = e[i * 4 + 3] * inv;
        *(float4*)(p + i * 128 + lane * 4) = o;
        uint2 u;
        u.x = (uint32_t)h1(o.x) | ((uint32_t)h1(o.y) << 16);
        u.y = (uint32_t)h1(o.z) | ((uint32_t)h1(o.w) << 16);
        *(uint2*)(at16 + base + i * 128 + lane * 4) = u;
    }
}

/* ------------------------------------------------------------------ */
/* Kernel: ax = attn @ x (plain fp16). grid (4,4,32), 2 CTAs/SM.       */
/* ------------------------------------------------------------------ */
__global__ __launch_bounds__(256, 2) void ax_kernel() {
    extern __shared__ uint16_t dynsm[];

    const int tid = threadIdx.x;
    const int lane = tid & 31;
    const int wid = tid >> 5;
    const int wm = wid & 1;
    const int wn = wid >> 1;
    const int b = blockIdx.z;
    const int row0 = blockIdx.y * 128;
    const int col0 = blockIdx.x * 128;

    const uint16_t* A = at16 + ((size_t)b * 512 + row0) * 512;
    const uint16_t* B = xt16 + ((size_t)b * 512 + col0) * 512;

    float acc[4][4][4] = {};
    gemm128_body(A, B, sptr(dynsm), tid, wm, wn, lane, acc);

    const size_t rowg = (size_t)b * 512;
    const int g = lane >> 2;
    const int tg2 = (lane & 3) * 2;
#pragma unroll
    for (int mt = 0; mt < 4; mt++) {
        int r = row0 + wm * 64 + mt * 16 + g;
#pragma unroll
        for (int nt = 0; nt < 4; nt++) {
            int c = col0 + wn * 32 + nt * 8 + tg2;
            __half2 p0 = __floats2half2_rn(acc[mt][nt][0], acc[mt][nt][1]);
            __half2 p1 = __floats2half2_rn(acc[mt][nt][2], acc[mt][nt][3]);
            *(uint32_t*)(ax16 + (rowg + r) * 512 + c) = *reinterpret_cast<uint32_t*>(&p0);
            *(uint32_t*)(ax16 + (rowg + r + 8) * 512 + c) = *reinterpret_cast<uint32_t*>(&p1);
        }
    }
}

/* ------------------------------------------------------------------ */
/* Kernel: split-K partials of out = ax.reshape(32,262144) @ Wm.       */
/* grid (4, KSPLIT=64) = 256 CTAs (single wave at 2 CTAs/SM).          */
/* ------------------------------------------------------------------ */
#define FAEL (32 * ASTR)
#define FBEL (128 * ASTR)
#define FSTAGE (FAEL + FBEL)

__global__ __launch_bounds__(256, 2) void final_kernel(const float* __restrict__ Wm) {
    __shared__ alignas(16) uint16_t dsm[2 * FSTAGE];

    const int tid = threadIdx.x;
    const int lane = tid & 31;
    const int wid = tid >> 5;
    const int col0 = blockIdx.x * 128;
    const size_t kbase = (size_t)blockIdx.y * KCHUNK;

    float acc[2][2][4] = {};
    uint2 va;
    float4 vb[4];
    const int am = tid >> 3;
    const int ak = (tid & 7) * 4;

    va = *(const uint2*)(ax16 + (size_t)am * 262144 + kbase + ak);
#pragma unroll
    for (int i = 0; i < 4; i++) {
        int idx = i * 256 + tid;
        vb[i] = *(const float4*)(Wm + (kbase + (idx >> 5)) * 512 + col0 + (idx & 31) * 4);
    }

    auto store_stage = [&](uint16_t* stg) {
        *(uint2*)(stg + am * ASTR + ak) = va;
        uint16_t* bh = stg + FAEL;
#pragma unroll
        for (int i = 0; i < 4; i++) {
            int idx = i * 256 + tid;
            int k = idx >> 5;
            int n = (idx & 31) * 4;
            bh[(n + 0) * ASTR + k] = h1(vb[i].x);
            bh[(n + 1) * ASTR + k] = h1(vb[i].y);
            bh[(n + 2) * ASTR + k] = h1(vb[i].z);
            bh[(n + 3) * ASTR + k] = h1(vb[i].w);
        }
    };

    store_stage(dsm);
    va = *(const uint2*)(ax16 + (size_t)am * 262144 + kbase + BK + ak);
#pragma unroll
    for (int i = 0; i < 4; i++) {
        int idx = i * 256 + tid;
        vb[i] = *(const float4*)(Wm + (kbase + BK + (idx >> 5)) * 512 + col0 + (idx & 31) * 4);
    }
    __syncthreads();

    const int lr = (lane & 7) + ((lane >> 3) & 1) * 8;
    const int lc = (lane >> 4) * 8;

    for (int k0 = 0; k0 < KCHUNK; k0 += BK) {
        int cur = (k0 >> 5) & 1;
        if (k0 + BK < KCHUNK) {
            store_stage(dsm + (cur ^ 1) * FSTAGE);
        }
        if (k0 + 2 * BK < KCHUNK) {
            va = *(const uint2*)(ax16 + (size_t)am * 262144 + kbase + k0 + 2 * BK + ak);
#pragma unroll
            for (int i = 0; i < 4; i++) {
                int idx = i * 256 + tid;
                vb[i] = *(const float4*)(Wm + (kbase + k0 + 2 * BK + (idx >> 5)) * 512 +
                                         col0 + (idx & 31) * 4);
            }
        }
        uint32_t base = sptr(dsm) + cur * FSTAGE * 2;
        uint32_t sA = base;
        uint32_t sB = base + FAEL * 2;
#pragma unroll
        for (int ks = 0; ks < BK; ks += 16) {
            uint32_t bf[2][2];
            uint32_t offb = (uint32_t)(((wid * 16 + lr) * ASTR + ks + lc) * 2);
            uint32_t r0, r1, r2, r3;
            ldsm_x4(r0, r1, r2, r3, sB + offb);
            bf[0][0] = r0;
            bf[0][1] = r2;
            bf[1][0] = r1;
            bf[1][1] = r3;
            uint32_t a[2][4];
#pragma unroll
            for (int mt = 0; mt < 2; mt++) {
                uint32_t offa = (uint32_t)(((mt * 16 + lr) * ASTR + ks + lc) * 2);
                ldsm_x4(a[mt][0], a[mt][1], a[mt][2], a[mt][3], sA + offa);
            }
#pragma unroll
            for (int mt = 0; mt < 2; mt++) {
#pragma unroll
                for (int nt = 0; nt < 2; nt++) {
                    mma_f16(acc[mt][nt], a[mt], bf[nt]);
                }
            }
        }
        __syncthreads();
    }

    const int g = lane >> 2;
    const int tg2 = (lane & 3) * 2;
    float* P = g_part + (size_t)blockIdx.y * 16384;
#pragma unroll
    for (int mt = 0; mt < 2; mt++) {
        int r = mt * 16 + g;
#pragma unroll
        for (int nt = 0; nt < 2; nt++) {
            int c = col0 + wid * 16 + nt * 8 + tg2;
            float2 o0;
            float2 o1;
            o0.x = acc[mt][nt][0];
            o0.y = acc[mt][nt][1];
            o1.x = acc[mt][nt][2];
            o1.y = acc[mt][nt][3];
            *(float2*)(P + (size_t)r * 512 + c) = o0;
            *(float2*)(P + (size_t)(r + 8) * 512 + c) = o1;
        }
    }
}

/* ------------------------------------------------------------------ */
/* Kernel: deterministic split-K reduce + bias. grid 64 x 256.         */
/* ------------------------------------------------------------------ */
__global__ __launch_bounds__(256) void reduce_kernel(float* __restrict__ out,
                                                     const float* __restrict__ bm) {
    const int idx = blockIdx.x * 256 + threadIdx.x;
    const int n = idx & 511;
    float sum = bm[n];
#pragma unroll 8
    for (int s = 0; s < KSPLIT; s++) {
        sum += g_part[(size_t)s * 16384 + idx];
    }
    out[idx] = sum;
}

/* ------------------------------------------------------------------ */
extern "C" void kernel_launch(void* const* d_in, const int* in_sizes, int n_in,
                              void* d_out, int out_size) {
    const float* x = (const float*)d_in[0];
    const float* Wq = (const float*)d_in[1];
    const float* bq = (const float*)d_in[2];
    const float* Wk = (const float*)d_in[3];
    const float* bk = (const float*)d_in[4];
    const float* Wm = (const float*)d_in[5];
    const float* bm = (const float*)d_in[6];

    float* out = (float*)d_out;   /* [32, 512] */
    float* attn = out + 32 * 512; /* [32, 512, 512] */

    cudaFuncSetAttribute(proj_kernel, cudaFuncAttributeMaxDynamicSharedMemorySize,
                         GSMEM_BYTES);
    cudaFuncSetAttribute(scores_kernel, cudaFuncAttributeMaxDynamicSharedMemorySize,
                         GSMEM_BYTES);
    cudaFuncSetAttribute(ax_kernel, cudaFuncAttributeMaxDynamicSharedMemorySize,
                         GSMEM_BYTES);

    prep_x<<<dim3(8, 8, 32), 256>>>(x);
    prep_wt<<<dim3(8, 8, 2), 256>>>(Wq, Wk);
    proj_kernel<<<dim3(4, 128, 2), 256, GSMEM_BYTES>>>(bq, bk);
    scores_kernel<<<dim3(4, 4, 32), 256, GSMEM_BYTES>>>(attn);
    softmax_kernel<<<2048, 256>>>(attn);
    ax_kernel<<<dim3(4, 4, 32), 256, GSMEM_BYTES>>>();
    final_kernel<<<dim3(4, KSPLIT), 256>>>(Wm);
    reduce_kernel<<<64, 256>>>(out, bm);
}

// round 9
// speedup vs baseline: 4.9877x; 1.7648x over previous
#include <cuda_runtime.h>
#include <cuda_fp16.h>
#include <stdint.h>
#include <math.h>

#define ASTR 40            /* padded smem stride in fp16 elems (80B rows) */
#define BK 32
#define NITER 16           /* K=512 / BK */
#define STAGES 4
#define KSPLIT 64
#define KCHUNK 4096
#define BN_LD 136          /* final kernel B smem stride ([k][n] layout) */

/* Scratch: __device__ globals (allocation-free rule) */
__device__ uint16_t xd16[32 * 512 * 512];   /* x direct fp16 [b*512+n][h] */
__device__ uint16_t xt16[32 * 512 * 512];   /* x^T fp16 [b][h][m] */
__device__ uint16_t wt16[2 * 512 * 512];    /* Wq^T, Wk^T fp16 [z][n][k] */
__device__ uint16_t q16[32 * 512 * 512];    /* q fp16 */
__device__ uint16_t k16[32 * 512 * 512];    /* k fp16 */
__device__ uint16_t at16[32 * 512 * 512];   /* softmax(attn) fp16 */
__device__ uint16_t ax16[32 * 512 * 512];   /* attn@x fp16 */
__device__ float g_part[KSPLIT * 32 * 512];

/* ------------------------------------------------------------------ */
/* Helpers                                                             */
/* ------------------------------------------------------------------ */
__device__ __forceinline__ uint32_t sptr(const void* p) {
    return (uint32_t)__cvta_generic_to_shared(p);
}

__device__ __forceinline__ void ldsm_x4(uint32_t& r0, uint32_t& r1,
                                        uint32_t& r2, uint32_t& r3,
                                        uint32_t addr) {
    asm volatile("ldmatrix.sync.aligned.m8n8.x4.shared.b16 {%0,%1,%2,%3}, [%4];"
                 : "=r"(r0), "=r"(r1), "=r"(r2), "=r"(r3)
                 : "r"(addr));
}

__device__ __forceinline__ void ldsm_x4_trans(uint32_t& r0, uint32_t& r1,
                                              uint32_t& r2, uint32_t& r3,
                                              uint32_t addr) {
    asm volatile("ldmatrix.sync.aligned.m8n8.x4.trans.shared.b16 {%0,%1,%2,%3}, [%4];"
                 : "=r"(r0), "=r"(r1), "=r"(r2), "=r"(r3)
                 : "r"(addr));
}

__device__ __forceinline__ void mma_f16(float* c, const uint32_t* a,
                                        const uint32_t* b) {
    asm volatile(
        "mma.sync.aligned.m16n8k16.row.col.f32.f16.f16.f32 "
        "{%0,%1,%2,%3}, {%4,%5,%6,%7}, {%8,%9}, {%0,%1,%2,%3};"
        : "+f"(c[0]), "+f"(c[1]), "+f"(c[2]), "+f"(c[3])
        : "r"(a[0]), "r"(a[1]), "r"(a[2]), "r"(a[3]),
          "r"(b[0]), "r"(b[1]));
}

__device__ __forceinline__ void cpa16(uint32_t dst, const void* src) {
    asm volatile("cp.async.cg.shared.global [%0], [%1], 16;"
                 :: "r"(dst), "l"(src) : "memory");
}
__device__ __forceinline__ void cpa_commit() {
    asm volatile("cp.async.commit_group;" ::: "memory");
}
template <int N>
__device__ __forceinline__ void cpa_wait() {
    asm volatile("cp.async.wait_group %0;" :: "n"(N) : "memory");
}

__device__ __forceinline__ uint16_t h1(float v) {
    __half h = __float2half_rn(v);
    return *reinterpret_cast<uint16_t*>(&h);
}

__device__ __forceinline__ void pack8_plain(const float* v, uint4& u) {
    uint16_t h[8];
#pragma unroll
    for (int j = 0; j < 8; j++) {
        h[j] = h1(v[j]);
    }
    u.x = (uint32_t)h[0] | ((uint32_t)h[1] << 16);
    u.y = (uint32_t)h[2] | ((uint32_t)h[3] << 16);
    u.z = (uint32_t)h[4] | ((uint32_t)h[5] << 16);
    u.w = (uint32_t)h[6] | ((uint32_t)h[7] << 16);
}

/* copy one 128x32 fp16 tile (src ld=512, pre-offset by k0) into smem  */
__device__ __forceinline__ void cpa_tile(uint32_t sdst, const uint16_t* src,
                                         int tid) {
#pragma unroll
    for (int i = 0; i < 2; i++) {
        int q = i * 256 + tid;
        int row = q >> 2;
        int c = (q & 3) * 8;
        cpa16(sdst + (uint32_t)(row * ASTR + c) * 2, src + (size_t)row * 512 + c);
    }
}

/* ------------------------------------------------------------------ */
/* Compute: one BK=32 slab, 128x128 CTA tile, plain fp16. 8 warps.     */
/* ------------------------------------------------------------------ */
__device__ __forceinline__ void compute128_h(uint32_t sA, uint32_t sB,
                                             int wm, int wn, int lane,
                                             float acc[4][4][4]) {
    const int lr = (lane & 7) + ((lane >> 3) & 1) * 8;
    const int lc = (lane >> 4) * 8;
#pragma unroll
    for (int ks = 0; ks < BK; ks += 16) {
        uint32_t b[4][2];
#pragma unroll
        for (int p = 0; p < 2; p++) {
            uint32_t off = (uint32_t)(((wn * 32 + p * 16 + lr) * ASTR + ks + lc) * 2);
            uint32_t r0, r1, r2, r3;
            ldsm_x4(r0, r1, r2, r3, sB + off);
            b[2 * p][0] = r0;
            b[2 * p][1] = r2;
            b[2 * p + 1][0] = r1;
            b[2 * p + 1][1] = r3;
        }
        uint32_t a[4][4];
#pragma unroll
        for (int mt = 0; mt < 4; mt++) {
            uint32_t off = (uint32_t)(((wm * 64 + mt * 16 + lr) * ASTR + ks + lc) * 2);
            ldsm_x4(a[mt][0], a[mt][1], a[mt][2], a[mt][3], sA + off);
        }
#pragma unroll
        for (int mt = 0; mt < 4; mt++) {
#pragma unroll
            for (int nt = 0; nt < 4; nt++) {
                mma_f16(acc[mt][nt], a[mt], b[nt]);
            }
        }
    }
}

/* ------------------------------------------------------------------ */
/* Prep 1: x -> direct fp16 (xd16) AND transposed fp16 (xt16).         */
/* ------------------------------------------------------------------ */
__global__ __launch_bounds__(256) void prep_x(const float* __restrict__ x) {
    __shared__ float ts[64][65];
    const int tid = threadIdx.x;
    const int m0 = blockIdx.y * 64;
    const int h0 = blockIdx.x * 64;
    const size_t off = (size_t)blockIdx.z * 262144;
    const float* src = x + off + (size_t)m0 * 512 + h0;

#pragma unroll
    for (int i = 0; i < 4; i++) {
        int lin = i * 256 + tid;
        int r = lin >> 4;
        int c4 = (lin & 15) * 4;
        float4 v = *(const float4*)(src + (size_t)r * 512 + c4);
        ts[r][c4 + 0] = v.x;
        ts[r][c4 + 1] = v.y;
        ts[r][c4 + 2] = v.z;
        ts[r][c4 + 3] = v.w;
    }
    __syncthreads();

#pragma unroll
    for (int i = 0; i < 2; i++) {
        int lin = i * 256 + tid;
        int r = lin >> 3;
        int c8 = (lin & 7) * 8;
        float v[8];
#pragma unroll
        for (int j = 0; j < 8; j++) {
            v[j] = ts[r][c8 + j];
        }
        uint4 u;
        pack8_plain(v, u);
        *(uint4*)(xd16 + off + (size_t)(m0 + r) * 512 + h0 + c8) = u;
    }
#pragma unroll
    for (int i = 0; i < 2; i++) {
        int lin = i * 256 + tid;
        int hr = lin >> 3;
        int m8 = (lin & 7) * 8;
        float v[8];
#pragma unroll
        for (int j = 0; j < 8; j++) {
            v[j] = ts[m8 + j][hr];
        }
        uint4 u;
        pack8_plain(v, u);
        *(uint4*)(xt16 + off + (size_t)(h0 + hr) * 512 + m0 + m8) = u;
    }
}

/* ------------------------------------------------------------------ */
/* Prep 2: Wq/Wk -> transposed plain fp16 (wt16). grid (8,8,2).        */
/* ------------------------------------------------------------------ */
__global__ __launch_bounds__(256) void prep_wt(const float* __restrict__ Wq,
                                               const float* __restrict__ Wk) {
    __shared__ float ts[64][65];
    const int tid = threadIdx.x;
    const int k0 = blockIdx.y * 64;
    const int n0 = blockIdx.x * 64;
    const float* src = (blockIdx.z ? Wk : Wq) + (size_t)k0 * 512 + n0;
    const size_t dstoff = (size_t)blockIdx.z * 262144;

#pragma unroll
    for (int i = 0; i < 4; i++) {
        int lin = i * 256 + tid;
        int r = lin >> 4;
        int c4 = (lin & 15) * 4;
        float4 v = *(const float4*)(src + (size_t)r * 512 + c4);
        ts[r][c4 + 0] = v.x;
        ts[r][c4 + 1] = v.y;
        ts[r][c4 + 2] = v.z;
        ts[r][c4 + 3] = v.w;
    }
    __syncthreads();

#pragma unroll
    for (int i = 0; i < 2; i++) {
        int lin = i * 256 + tid;
        int nr = lin >> 3;
        int k8 = (lin & 7) * 8;
        float v[8];
#pragma unroll
        for (int j = 0; j < 8; j++) {
            v[j] = ts[k8 + j][nr];
        }
        uint4 u;
        pack8_plain(v, u);
        *(uint4*)(wt16 + dstoff + (size_t)(n0 + nr) * 512 + k0 + k8) = u;
    }
}

/* ------------------------------------------------------------------ */
/* Generic plain-fp16 GEMM body: 4-stage cp.async pipeline.            */
/* ------------------------------------------------------------------ */
#define PTILE (128 * ASTR)
#define STAGE_BYTES (2 * PTILE * 2)
#define GSMEM_BYTES (STAGES * STAGE_BYTES)   /* 81920 */

__device__ __forceinline__ void gemm128_body(
    const uint16_t* __restrict__ A, const uint16_t* __restrict__ B,
    uint32_t s0, int tid, int wm, int wn, int lane, float acc[4][4][4]) {
#pragma unroll
    for (int s = 0; s < STAGES - 1; s++) {
        uint32_t sb = s0 + s * STAGE_BYTES;
        cpa_tile(sb, A + s * BK, tid);
        cpa_tile(sb + PTILE * 2, B + s * BK, tid);
        cpa_commit();
    }

    for (int c = 0; c < NITER; c++) {
        cpa_wait<STAGES - 2>();
        __syncthreads();
        int nf = c + STAGES - 1;
        if (nf < NITER) {
            uint32_t sb = s0 + (nf & (STAGES - 1)) * STAGE_BYTES;
            cpa_tile(sb, A + nf * BK, tid);
            cpa_tile(sb + PTILE * 2, B + nf * BK, tid);
        }
        cpa_commit();   /* unconditional: keeps group count in lockstep */
        uint32_t sb = s0 + (c & (STAGES - 1)) * STAGE_BYTES;
        compute128_h(sb, sb + PTILE * 2, wm, wn, lane, acc);
    }
}

/* ------------------------------------------------------------------ */
/* Kernel: q/k projections. grid (4, 128, 2), dyn smem, 2 CTAs/SM.     */
/* ------------------------------------------------------------------ */
__global__ __launch_bounds__(256, 2) void proj_kernel(
    const float* __restrict__ bq, const float* __restrict__ bk) {
    extern __shared__ uint16_t dynsm[];

    const int tid = threadIdx.x;
    const int lane = tid & 31;
    const int wid = tid >> 5;
    const int wm = wid & 1;
    const int wn = wid >> 1;
    const int z = blockIdx.z;
    const int row0 = blockIdx.y * 128;
    const int col0 = blockIdx.x * 128;

    const uint16_t* A = xd16 + (size_t)row0 * 512;
    const uint16_t* B = wt16 + (size_t)z * 262144 + (size_t)col0 * 512;

    float acc[4][4][4] = {};
    gemm128_body(A, B, sptr(dynsm), tid, wm, wn, lane, acc);

    const float* bias = z ? bk : bq;
    uint16_t* O = z ? k16 : q16;
    const int g = lane >> 2;
    const int tg2 = (lane & 3) * 2;
#pragma unroll
    for (int mt = 0; mt < 4; mt++) {
        int r = row0 + wm * 64 + mt * 16 + g;
#pragma unroll
        for (int nt = 0; nt < 4; nt++) {
            int c = col0 + wn * 32 + nt * 8 + tg2;
            float2 bv = *(const float2*)(bias + c);
            __half2 p0 = __floats2half2_rn(acc[mt][nt][0] + bv.x, acc[mt][nt][1] + bv.y);
            __half2 p1 = __floats2half2_rn(acc[mt][nt][2] + bv.x, acc[mt][nt][3] + bv.y);
            *(uint32_t*)(O + (size_t)r * 512 + c) = *reinterpret_cast<uint32_t*>(&p0);
            *(uint32_t*)(O + (size_t)(r + 8) * 512 + c) = *reinterpret_cast<uint32_t*>(&p1);
        }
    }
}

/* ------------------------------------------------------------------ */
/* Kernel: scores = sigmoid(q k^T / sqrt(512)). grid (4,4,32).         */
/* ------------------------------------------------------------------ */
__global__ __launch_bounds__(256, 2) void scores_kernel(float* __restrict__ attn) {
    extern __shared__ uint16_t dynsm[];

    const int tid = threadIdx.x;
    const int lane = tid & 31;
    const int wid = tid >> 5;
    const int wm = wid & 1;
    const int wn = wid >> 1;
    const int b = blockIdx.z;
    const int row0 = blockIdx.y * 128;
    const int col0 = blockIdx.x * 128;

    const uint16_t* A = q16 + ((size_t)b * 512 + row0) * 512;
    const uint16_t* B = k16 + ((size_t)b * 512 + col0) * 512;

    float acc[4][4][4] = {};
    gemm128_body(A, B, sptr(dynsm), tid, wm, wn, lane, acc);

    const float scale = 0.04419417382415922f; /* 1/sqrt(512) */
    float* S = attn + (size_t)b * 262144;
    const int g = lane >> 2;
    const int tg2 = (lane & 3) * 2;
#pragma unroll
    for (int mt = 0; mt < 4; mt++) {
        int r = row0 + wm * 64 + mt * 16 + g;
#pragma unroll
        for (int nt = 0; nt < 4; nt++) {
            int c = col0 + wn * 32 + nt * 8 + tg2;
            float2 o0;
            float2 o1;
            o0.x = 1.f / (1.f + expf(-acc[mt][nt][0] * scale));
            o0.y = 1.f / (1.f + expf(-acc[mt][nt][1] * scale));
            o1.x = 1.f / (1.f + expf(-acc[mt][nt][2] * scale));
            o1.y = 1.f / (1.f + expf(-acc[mt][nt][3] * scale));
            *(float2*)(S + (size_t)r * 512 + c) = o0;
            *(float2*)(S + (size_t)(r + 8) * 512 + c) = o1;
        }
    }
}

/* ------------------------------------------------------------------ */
/* Kernel: warp-per-row softmax in-place + fp16 copy. grid 2048.       */
/* ------------------------------------------------------------------ */
__global__ __launch_bounds__(256) void softmax_kernel(float* __restrict__ attn) {
    const int w = threadIdx.x >> 5;
    const int lane = threadIdx.x & 31;
    const size_t base = ((size_t)blockIdx.x * 8 + w) * 512;
    float* p = attn + base;

    float4 v[4];
#pragma unroll
    for (int i = 0; i < 4; i++) {
        v[i] = *(const float4*)(p + i * 128 + lane * 4);
    }
    float e[16];
    float s = 0.f;
#pragma unroll
    for (int i = 0; i < 4; i++) {
        e[i * 4 + 0] = expf(v[i].x);
        e[i * 4 + 1] = expf(v[i].y);
        e[i * 4 + 2] = expf(v[i].z);
        e[i * 4 + 3] = expf(v[i].w);
        s += e[i * 4 + 0] + e[i * 4 + 1] + e[i * 4 + 2] + e[i * 4 + 3];
    }
#pragma unroll
    for (int o = 16; o > 0; o >>= 1) {
        s += __shfl_xor_sync(0xffffffffu, s, o);
    }
    const float inv = 1.f / s;
#pragma unroll
    for (int i = 0; i < 4; i++) {
        float4 o;
        o.x = e[i * 4 + 0] * inv;
        o.y = e[i * 4 + 1] * inv;
        o.z = e[i * 4 + 2] * inv;
        o.w = e[i * 4 + 3] * inv;
        *(float4*)(p + i * 128 + lane * 4) = o;
        uint2 u;
        u.x = (uint32_t)h1(o.x) | ((uint32_t)h1(o.y) << 16);
        u.y = (uint32_t)h1(o.z) | ((uint32_t)h1(o.w) << 16);
        *(uint2*)(at16 + base + i * 128 + lane * 4) = u;
    }
}

/* ------------------------------------------------------------------ */
/* Kernel: ax = attn @ x (plain fp16). grid (4,4,32), 2 CTAs/SM.       */
/* ------------------------------------------------------------------ */
__global__ __launch_bounds__(256, 2) void ax_kernel() {
    extern __shared__ uint16_t dynsm[];

    const int tid = threadIdx.x;
    const int lane = tid & 31;
    const int wid = tid >> 5;
    const int wm = wid & 1;
    const int wn = wid >> 1;
    const int b = blockIdx.z;
    const int row0 = blockIdx.y * 128;
    const int col0 = blockIdx.x * 128;

    const uint16_t* A = at16 + ((size_t)b * 512 + row0) * 512;
    const uint16_t* B = xt16 + ((size_t)b * 512 + col0) * 512;

    float acc[4][4][4] = {};
    gemm128_body(A, B, sptr(dynsm), tid, wm, wn, lane, acc);

    const size_t rowg = (size_t)b * 512;
    const int g = lane >> 2;
    const int tg2 = (lane & 3) * 2;
#pragma unroll
    for (int mt = 0; mt < 4; mt++) {
        int r = row0 + wm * 64 + mt * 16 + g;
#pragma unroll
        for (int nt = 0; nt < 4; nt++) {
            int c = col0 + wn * 32 + nt * 8 + tg2;
            __half2 p0 = __floats2half2_rn(acc[mt][nt][0], acc[mt][nt][1]);
            __half2 p1 = __floats2half2_rn(acc[mt][nt][2], acc[mt][nt][3]);
            *(uint32_t*)(ax16 + (rowg + r) * 512 + c) = *reinterpret_cast<uint32_t*>(&p0);
            *(uint32_t*)(ax16 + (rowg + r + 8) * 512 + c) = *reinterpret_cast<uint32_t*>(&p1);
        }
    }
}

/* ------------------------------------------------------------------ */
/* Kernel: split-K partials of out = ax.reshape(32,262144) @ Wm.       */
/* B kept in native [k][n] smem layout (vectorized fp16 stores),       */
/* fragments fetched with ldmatrix.trans. grid (4, KSPLIT=64).         */
/* ------------------------------------------------------------------ */
#define FAEL (32 * ASTR)               /* A stage elems: [m][k] */
#define FBEL (32 * BN_LD)              /* B stage elems: [k][n] */
#define FSTAGE (FAEL + FBEL)

__global__ __launch_bounds__(256, 2) void final_kernel(const float* __restrict__ Wm) {
    __shared__ alignas(16) uint16_t dsm[2 * FSTAGE];

    const int tid = threadIdx.x;
    const int lane = tid & 31;
    const int wid = tid >> 5;
    const int col0 = blockIdx.x * 128;
    const size_t kbase = (size_t)blockIdx.y * KCHUNK;

    float acc[2][2][4] = {};
    uint2 va;
    float4 vb[4];
    const int am = tid >> 3;
    const int ak = (tid & 7) * 4;
    const int bk_r = tid >> 5;          /* B rows: handled 8 per pass */
    const int bn4 = (tid & 31) * 4;     /* B cols: 4 n per thread     */

    va = *(const uint2*)(ax16 + (size_t)am * 262144 + kbase + ak);
#pragma unroll
    for (int i = 0; i < 4; i++) {
        vb[i] = *(const float4*)(Wm + (kbase + bk_r + i * 8) * 512 + col0 + bn4);
    }

    auto store_stage = [&](uint16_t* stg) {
        *(uint2*)(stg + am * ASTR + ak) = va;
        uint16_t* bs = stg + FAEL;
#pragma unroll
        for (int i = 0; i < 4; i++) {
            __half2 p0 = __floats2half2_rn(vb[i].x, vb[i].y);
            __half2 p1 = __floats2half2_rn(vb[i].z, vb[i].w);
            uint2 u;
            u.x = *reinterpret_cast<uint32_t*>(&p0);
            u.y = *reinterpret_cast<uint32_t*>(&p1);
            *(uint2*)(bs + (bk_r + i * 8) * BN_LD + bn4) = u;
        }
    };

    store_stage(dsm);
    va = *(const uint2*)(ax16 + (size_t)am * 262144 + kbase + BK + ak);
#pragma unroll
    for (int i = 0; i < 4; i++) {
        vb[i] = *(const float4*)(Wm + (kbase + BK + bk_r + i * 8) * 512 + col0 + bn4);
    }
    __syncthreads();

    const int lr = (lane & 7) + ((lane >> 3) & 1) * 8;
    const int lc = (lane >> 4) * 8;
    /* trans-ldsm B address pieces: row = ks + (lane>>4)*8 + (lane&7),
       col = n0 + ((lane>>3)&1)*8                                      */
    const int trow = (lane >> 4) * 8 + (lane & 7);
    const int tcol = ((lane >> 3) & 1) * 8;

    for (int k0 = 0; k0 < KCHUNK; k0 += BK) {
        int cur = (k0 >> 5) & 1;
        if (k0 + BK < KCHUNK) {
            store_stage(dsm + (cur ^ 1) * FSTAGE);
        }
        if (k0 + 2 * BK < KCHUNK) {
            va = *(const uint2*)(ax16 + (size_t)am * 262144 + kbase + k0 + 2 * BK + ak);
#pragma unroll
            for (int i = 0; i < 4; i++) {
                vb[i] = *(const float4*)(Wm + (kbase + k0 + 2 * BK + bk_r + i * 8) * 512 +
                                         col0 + bn4);
            }
        }
        uint32_t base = sptr(dsm) + cur * FSTAGE * 2;
        uint32_t sA = base;
        uint32_t sB = base + FAEL * 2;
#pragma unroll
        for (int ks = 0; ks < BK; ks += 16) {
            uint32_t bf[2][2];
            uint32_t offb = (uint32_t)(((ks + trow) * BN_LD + wid * 16 + tcol) * 2);
            uint32_t r0, r1, r2, r3;
            ldsm_x4_trans(r0, r1, r2, r3, sB + offb);
            bf[0][0] = r0;
            bf[1][0] = r1;
            bf[0][1] = r2;
            bf[1][1] = r3;
            uint32_t a[2][4];
#pragma unroll
            for (int mt = 0; mt < 2; mt++) {
                uint32_t offa = (uint32_t)(((mt * 16 + lr) * ASTR + ks + lc) * 2);
                ldsm_x4(a[mt][0], a[mt][1], a[mt][2], a[mt][3], sA + offa);
            }
#pragma unroll
            for (int mt = 0; mt < 2; mt++) {
#pragma unroll
                for (int nt = 0; nt < 2; nt++) {
                    mma_f16(acc[mt][nt], a[mt], bf[nt]);
                }
            }
        }
        __syncthreads();
    }

    const int g = lane >> 2;
    const int tg2 = (lane & 3) * 2;
    float* P = g_part + (size_t)blockIdx.y * 16384;
#pragma unroll
    for (int mt = 0; mt < 2; mt++) {
        int r = mt * 16 + g;
#pragma unroll
        for (int nt = 0; nt < 2; nt++) {
            int c = col0 + wid * 16 + nt * 8 + tg2;
            float2 o0;
            float2 o1;
            o0.x = acc[mt][nt][0];
            o0.y = acc[mt][nt][1];
            o1.x = acc[mt][nt][2];
            o1.y = acc[mt][nt][3];
            *(float2*)(P + (size_t)r * 512 + c) = o0;
            *(float2*)(P + (size_t)(r + 8) * 512 + c) = o1;
        }
    }
}

/* ------------------------------------------------------------------ */
/* Kernel: deterministic split-K reduce + bias. grid 64 x 256.         */
/* ------------------------------------------------------------------ */
__global__ __launch_bounds__(256) void reduce_kernel(float* __restrict__ out,
                                                     const float* __restrict__ bm) {
    const int idx = blockIdx.x * 256 + threadIdx.x;
    const int n = idx & 511;
    float sum = bm[n];
#pragma unroll 8
    for (int s = 0; s < KSPLIT; s++) {
        sum += g_part[(size_t)s * 16384 + idx];
    }
    out[idx] = sum;
}

/* ------------------------------------------------------------------ */
extern "C" void kernel_launch(void* const* d_in, const int* in_sizes, int n_in,
                              void* d_out, int out_size) {
    const float* x = (const float*)d_in[0];
    const float* Wq = (const float*)d_in[1];
    const float* bq = (const float*)d_in[2];
    const float* Wk = (const float*)d_in[3];
    const float* bk = (const float*)d_in[4];
    const float* Wm = (const float*)d_in[5];
    const float* bm = (const float*)d_in[6];

    float* out = (float*)d_out;   /* [32, 512] */
    float* attn = out + 32 * 512; /* [32, 512, 512] */

    cudaFuncSetAttribute(proj_kernel, cudaFuncAttributeMaxDynamicSharedMemorySize,
                         GSMEM_BYTES);
    cudaFuncSetAttribute(scores_kernel, cudaFuncAttributeMaxDynamicSharedMemorySize,
                         GSMEM_BYTES);
    cudaFuncSetAttribute(ax_kernel, cudaFuncAttributeMaxDynamicSharedMemorySize,
                         GSMEM_BYTES);

    prep_x<<<dim3(8, 8, 32), 256>>>(x);
    prep_wt<<<dim3(8, 8, 2), 256>>>(Wq, Wk);
    proj_kernel<<<dim3(4, 128, 2), 256, GSMEM_BYTES>>>(bq, bk);
    scores_kernel<<<dim3(4, 4, 32), 256, GSMEM_BYTES>>>(attn);
    softmax_kernel<<<2048, 256>>>(attn);
    ax_kernel<<<dim3(4, 4, 32), 256, GSMEM_BYTES>>>();
    final_kernel<<<dim3(4, KSPLIT), 256>>>(Wm);
    reduce_kernel<<<64, 256>>>(out, bm);
}